// round 1
// baseline (speedup 1.0000x reference)
#include <cuda_runtime.h>
#include <math.h>

#define NT 512
#define NB 64
#define NI 1024
#define NH 256
#define NG 768   // 3*NH

// ---------------- scratch (device globals: no allocations allowed) ----------
__device__ float g_gx_f[NT * NB * NG];   // 100.7 MB
__device__ float g_gx_b[NT * NB * NG];   // 100.7 MB
__device__ float g_out_f[NT * NB * NH];  // 33.6 MB : fwd hidden history
__device__ float g_out_b[NT * NB * NH];  // 33.6 MB : bwd hidden history
__device__ unsigned g_flags[128 * 32];   // grid-barrier flags, 128B apart

__global__ void init_flags_kernel() {
    if (threadIdx.x < 128)
        ((volatile unsigned*)g_flags)[threadIdx.x * 32] = 0u;
}

// ---------------- Kernel 1: gx = src @ Wih^T + bih  (both directions) -------
// C[32768 x 1536], A = src (row-major, K=1024), B rows = Wih rows (K-major).
__global__ __launch_bounds__(256) void gemm_gx_kernel(
    const float* __restrict__ src,
    const float* __restrict__ Wih_f, const float* __restrict__ Wih_b,
    const float* __restrict__ bih_f, const float* __restrict__ bih_b)
{
    __shared__ float As[16][128];
    __shared__ float Bs[16][128];
    const int m0 = blockIdx.x * 128;
    const int n0 = blockIdx.y * 128;          // 0..1536, tiles never straddle 768
    const bool fwd = (n0 < NG);
    const float* Bmat = fwd ? (Wih_f + (size_t)n0 * NI) : (Wih_b + (size_t)(n0 - NG) * NI);
    const float* bias = fwd ? (bih_f + n0) : (bih_b + (n0 - NG));
    float* outp = fwd ? g_gx_f : g_gx_b;
    const int nc0 = fwd ? n0 : (n0 - NG);
    const int tid = threadIdx.x;
    const int tx = tid & 15, ty = tid >> 4;

    float acc[8][8];
#pragma unroll
    for (int i = 0; i < 8; i++)
#pragma unroll
        for (int j = 0; j < 8; j++) acc[i][j] = 0.f;

    for (int k0 = 0; k0 < NI; k0 += 16) {
#pragma unroll
        for (int i = 0; i < 2; i++) {
            int f = tid * 2 + i;               // 0..511
            int row = f >> 2, kc = (f & 3) * 4;
            float4 v = *(const float4*)(src + (size_t)(m0 + row) * NI + k0 + kc);
            As[kc][row] = v.x; As[kc + 1][row] = v.y; As[kc + 2][row] = v.z; As[kc + 3][row] = v.w;
            float4 w = *(const float4*)(Bmat + (size_t)row * NI + k0 + kc);
            Bs[kc][row] = w.x; Bs[kc + 1][row] = w.y; Bs[kc + 2][row] = w.z; Bs[kc + 3][row] = w.w;
        }
        __syncthreads();
#pragma unroll
        for (int k = 0; k < 16; k++) {
            float a[8], b[8];
            *(float4*)&a[0] = *(const float4*)&As[k][ty * 8];
            *(float4*)&a[4] = *(const float4*)&As[k][ty * 8 + 4];
            *(float4*)&b[0] = *(const float4*)&Bs[k][tx * 8];
            *(float4*)&b[4] = *(const float4*)&Bs[k][tx * 8 + 4];
#pragma unroll
            for (int i = 0; i < 8; i++)
#pragma unroll
                for (int j = 0; j < 8; j++) acc[i][j] += a[i] * b[j];
        }
        __syncthreads();
    }
    float bv[8];
#pragma unroll
    for (int j = 0; j < 8; j++) bv[j] = bias[tx * 8 + j];
#pragma unroll
    for (int i = 0; i < 8; i++) {
        const int m = m0 + ty * 8 + i;
        float4 o0, o1;
        o0.x = acc[i][0] + bv[0]; o0.y = acc[i][1] + bv[1];
        o0.z = acc[i][2] + bv[2]; o0.w = acc[i][3] + bv[3];
        o1.x = acc[i][4] + bv[4]; o1.y = acc[i][5] + bv[5];
        o1.z = acc[i][6] + bv[6]; o1.w = acc[i][7] + bv[7];
        float* op = outp + (size_t)m * NG + nc0 + tx * 8;
        *(float4*)op = o0;
        *(float4*)(op + 4) = o1;
    }
}

// ---------------- Kernel 2: persistent bidirectional GRU recurrence ---------
// 128 CTAs: 0..63 forward, 64..127 backward. Each CTA owns 4 h-columns
// (12 gate columns). Whh slice resident in smem. One grid barrier per step.
__global__ __launch_bounds__(256) void gru_rec_kernel(
    const float* __restrict__ Whh_f, const float* __restrict__ bhh_f,
    const float* __restrict__ Whh_b, const float* __restrict__ bhh_b)
{
    extern __shared__ float sm[];
    float* hs  = sm;                    // [64][260]  h_prev, padded rows
    float* ws  = sm + 64 * 260;         // [12][260]  Whh slice
    float* red = ws + 12 * 260;         // [8][32][24] k-split partials
    float* bs  = red + 8 * 32 * 24;     // [12] bhh slice (+pad)

    const int cta = blockIdx.x;
    const int tid = threadIdx.x;
    const int dir = cta >> 6;                // 0 fwd, 1 bwd
    const int j0  = (cta & 63) * 4;          // this CTA's h columns
    const float* Whh = dir ? Whh_b : Whh_f;
    const float* bhh = dir ? bhh_b : bhh_f;
    const float* gx  = dir ? g_gx_b : g_gx_f;
    float* out = dir ? g_out_b : g_out_f;

    // Resident weights: local col c = gate*4 + jj  ->  Whh row gate*256 + j0 + jj
    for (int idx = tid; idx < 12 * 256; idx += 256) {
        int c = idx >> 8, k = idx & 255;
        int gc = (c >> 2) * NH + j0 + (c & 3);
        ws[c * 260 + k] = Whh[(size_t)gc * NH + k];
    }
    if (tid < 12) bs[tid] = bhh[(tid >> 2) * NH + j0 + (tid & 3)];

    // compute-phase mapping: warp kg handles k-slice [kg*32, kg*32+32)
    const int kg = tid >> 5, lane = tid & 31;
    const int bq = lane & 7, cq = lane >> 3;   // thread tile: 8 rows x 3 cols
    const int kb = kg * 32;
    // gate-phase mapping: 256 threads = 64 b x 4 jj (jj contiguous -> coalesced)
    const int gb = tid >> 2, gj = tid & 3;
    __syncthreads();

    for (int s = 0; s < NT; s++) {
        const int t = dir ? (NT - 1 - s) : s;
        // stage h_prev into smem (rows padded to 260 for bank spread)
        if (s == 0) {
            for (int i = tid; i < 64 * 260; i += 256) hs[i] = 0.f;
        } else {
            const int tp = dir ? (t + 1) : (t - 1);
            const float4* hp = (const float4*)(out + (size_t)tp * NB * NH);
            for (int i = tid; i < NB * NH / 4; i += 256) {
                float4 v = __ldcg(hp + i);
                const int b = i >> 6, k4 = (i & 63) * 4;
                float* d = hs + b * 260 + k4;
                d[0] = v.x; d[1] = v.y; d[2] = v.z; d[3] = v.w;
            }
        }
        __syncthreads();

        // gh partials: each thread 8 rows (b = i*8 + bq) x 3 cols over 32 k
        float acc[8][3];
#pragma unroll
        for (int i = 0; i < 8; i++) { acc[i][0] = 0.f; acc[i][1] = 0.f; acc[i][2] = 0.f; }
        const float* w0 = ws + (cq * 3 + 0) * 260;
        const float* w1 = ws + (cq * 3 + 1) * 260;
        const float* w2 = ws + (cq * 3 + 2) * 260;
#pragma unroll 4
        for (int k = kb; k < kb + 32; k++) {
            const float f0 = w0[k], f1 = w1[k], f2 = w2[k];
#pragma unroll
            for (int i = 0; i < 8; i++) {
                const float h = hs[(i * 8 + bq) * 260 + k];
                acc[i][0] += h * f0; acc[i][1] += h * f1; acc[i][2] += h * f2;
            }
        }
        float* rp = red + kg * 768 + lane * 24;
#pragma unroll
        for (int i = 0; i < 8; i++) {
            rp[i * 3 + 0] = acc[i][0]; rp[i * 3 + 1] = acc[i][1]; rp[i * 3 + 2] = acc[i][2];
        }
        __syncthreads();

        // gate phase: thread -> (b=gb, jj=gj); reduce 8 k-partials per gate
        float gh[3];
#pragma unroll
        for (int g = 0; g < 3; g++) {
            const int c = g * 4 + gj;
            const int lane2 = (gb & 7) + (c / 3) * 8;
            const int oidx  = (gb >> 3) * 3 + (c % 3);
            float ssum = 0.f;
#pragma unroll
            for (int q = 0; q < 8; q++) ssum += red[q * 768 + lane2 * 24 + oidx];
            gh[g] = ssum + bs[c];
        }
        const float* gp = gx + ((size_t)t * NB + gb) * NG + j0 + gj;
        const float xr = gp[0], xz = gp[NH], xn = gp[2 * NH];
        const float r = 1.f / (1.f + expf(-(xr + gh[0])));
        const float z = 1.f / (1.f + expf(-(xz + gh[1])));
        const float n = tanhf(xn + r * gh[2]);
        const float hprev = hs[gb * 260 + j0 + gj];
        const float hnew = (1.f - z) * n + z * hprev;
        out[((size_t)t * NB + gb) * NH + j0 + gj] = hnew;

        // grid barrier: fence own stores, block-sync, publish, poll all flags
        __threadfence();
        __syncthreads();
        if (tid == 0) ((volatile unsigned*)g_flags)[cta * 32] = (unsigned)(s + 1);
        if (tid < 128) {
            const unsigned tgt = (unsigned)(s + 1);
            while (((volatile unsigned*)g_flags)[tid * 32] < tgt) __nanosleep(32);
        }
        __syncthreads();
    }
}

// ---------------- Kernel 3: outputs = [out_f|out_b] @ Wout^T + bout ---------
__global__ __launch_bounds__(256) void gemm_proj_kernel(
    const float* __restrict__ Wout, const float* __restrict__ bout,
    float* __restrict__ dst)
{
    __shared__ float As[16][128];
    __shared__ float Bs[16][128];
    const int m0 = blockIdx.x * 128;
    const int n0 = blockIdx.y * 128;        // 0 or 128
    const int tid = threadIdx.x;
    const int tx = tid & 15, ty = tid >> 4;

    float acc[8][8];
#pragma unroll
    for (int i = 0; i < 8; i++)
#pragma unroll
        for (int j = 0; j < 8; j++) acc[i][j] = 0.f;

    for (int k0 = 0; k0 < 512; k0 += 16) {
        const float* Asrc = (k0 < 256) ? g_out_f : g_out_b;
        const int kk0 = (k0 < 256) ? k0 : (k0 - 256);
#pragma unroll
        for (int i = 0; i < 2; i++) {
            int f = tid * 2 + i;
            int row = f >> 2, kc = (f & 3) * 4;
            float4 v = *(const float4*)(Asrc + (size_t)(m0 + row) * NH + kk0 + kc);
            As[kc][row] = v.x; As[kc + 1][row] = v.y; As[kc + 2][row] = v.z; As[kc + 3][row] = v.w;
            float4 w = *(const float4*)(Wout + (size_t)(n0 + row) * 512 + k0 + kc);
            Bs[kc][row] = w.x; Bs[kc + 1][row] = w.y; Bs[kc + 2][row] = w.z; Bs[kc + 3][row] = w.w;
        }
        __syncthreads();
#pragma unroll
        for (int k = 0; k < 16; k++) {
            float a[8], b[8];
            *(float4*)&a[0] = *(const float4*)&As[k][ty * 8];
            *(float4*)&a[4] = *(const float4*)&As[k][ty * 8 + 4];
            *(float4*)&b[0] = *(const float4*)&Bs[k][tx * 8];
            *(float4*)&b[4] = *(const float4*)&Bs[k][tx * 8 + 4];
#pragma unroll
            for (int i = 0; i < 8; i++)
#pragma unroll
                for (int j = 0; j < 8; j++) acc[i][j] += a[i] * b[j];
        }
        __syncthreads();
    }
    float bv[8];
#pragma unroll
    for (int j = 0; j < 8; j++) bv[j] = bout[n0 + tx * 8 + j];
#pragma unroll
    for (int i = 0; i < 8; i++) {
        const int m = m0 + ty * 8 + i;
        float4 o0, o1;
        o0.x = acc[i][0] + bv[0]; o0.y = acc[i][1] + bv[1];
        o0.z = acc[i][2] + bv[2]; o0.w = acc[i][3] + bv[3];
        o1.x = acc[i][4] + bv[4]; o1.y = acc[i][5] + bv[5];
        o1.z = acc[i][6] + bv[6]; o1.w = acc[i][7] + bv[7];
        float* op = dst + (size_t)m * NH + n0 + tx * 8;
        *(float4*)op = o0;
        *(float4*)(op + 4) = o1;
    }
}

// ---------------- Kernel 4: hidden = tanh([h_f|h_b] @ Whid^T + bhid) --------
__global__ __launch_bounds__(256) void hidden_kernel(
    const float* __restrict__ Whid, const float* __restrict__ bhid,
    float* __restrict__ outh)
{
    __shared__ float hc[512];
    const int b = blockIdx.x, tid = threadIdx.x;
    hc[tid]       = g_out_f[((size_t)(NT - 1) * NB + b) * NH + tid]; // fwd final h
    hc[256 + tid] = g_out_b[((size_t)b) * NH + tid];                 // bwd final h (t=0)
    __syncthreads();
    const float* w = Whid + (size_t)tid * 512;
    float ssum = bhid[tid];
#pragma unroll 8
    for (int k = 0; k < 512; k++) ssum += hc[k] * w[k];
    outh[(size_t)b * NH + tid] = tanhf(ssum);
}

// ---------------- launcher ---------------------------------------------------
extern "C" void kernel_launch(void* const* d_in, const int* in_sizes, int n_in,
                              void* d_out, int out_size)
{
    const float* src   = (const float*)d_in[0];
    const float* Wih_f = (const float*)d_in[1];
    const float* Whh_f = (const float*)d_in[2];
    const float* bih_f = (const float*)d_in[3];
    const float* bhh_f = (const float*)d_in[4];
    const float* Wih_b = (const float*)d_in[5];
    const float* Whh_b = (const float*)d_in[6];
    const float* bih_b = (const float*)d_in[7];
    const float* bhh_b = (const float*)d_in[8];
    const float* Wout  = (const float*)d_in[9];
    const float* bout  = (const float*)d_in[10];
    const float* Whid  = (const float*)d_in[11];
    const float* bhid  = (const float*)d_in[12];
    float* out = (float*)d_out;

    const int rec_smem = (64 * 260 + 12 * 260 + 8 * 32 * 24 + 16) * (int)sizeof(float);
    cudaFuncSetAttribute(gru_rec_kernel,
                         cudaFuncAttributeMaxDynamicSharedMemorySize, rec_smem);

    init_flags_kernel<<<1, 128>>>();
    gemm_gx_kernel<<<dim3(256, 12), 256>>>(src, Wih_f, Wih_b, bih_f, bih_b);
    gru_rec_kernel<<<128, 256, rec_smem>>>(Whh_f, bhh_f, Whh_b, bhh_b);
    gemm_proj_kernel<<<dim3(256, 2), 256>>>(Wout, bout, out);
    hidden_kernel<<<64, 256>>>(Whid, bhid, out + (size_t)NT * NB * NH);
}

// round 2
// speedup vs baseline: 1.1732x; 1.1732x over previous
#include <cuda_runtime.h>
#include <math.h>

#define NT 512
#define NB 64
#define NI 1024
#define NH 256
#define NG 768   // 3*NH

// ---------------- scratch (device globals: no allocations allowed) ----------
__device__ float g_gx_f[NT * NB * NG];   // 100.7 MB
__device__ float g_gx_b[NT * NB * NG];   // 100.7 MB
__device__ float g_out_f[NT * NB * NH];  // 33.6 MB : fwd hidden history
__device__ float g_out_b[NT * NB * NH];  // 33.6 MB : bwd hidden history
__device__ unsigned g_flags[128 * 32];   // grid-barrier flags, 128B apart

__global__ void init_flags_kernel() {
    if (threadIdx.x < 128)
        ((volatile unsigned*)g_flags)[threadIdx.x * 32] = 0u;
}

// ---------------- TF32 helpers ----------------------------------------------
__device__ __forceinline__ unsigned f2tf(float x) {
    unsigned r; asm("cvt.rna.tf32.f32 %0, %1;" : "=r"(r) : "f"(x)); return r;
}

#define MMA_TF32(d, a, b0, b1)                                                  \
    asm volatile("mma.sync.aligned.m16n8k8.row.col.f32.tf32.tf32.f32 "          \
        "{%0,%1,%2,%3}, {%4,%5,%6,%7}, {%8,%9}, {%0,%1,%2,%3};"                 \
        : "+f"(d[0]), "+f"(d[1]), "+f"(d[2]), "+f"(d[3])                        \
        : "r"(a[0]), "r"(a[1]), "r"(a[2]), "r"(a[3]), "r"(b0), "r"(b1))

// ---------------- Kernel 1: gx = src @ Wih^T + bih via 3xTF32 tensor cores --
// C[32768 x 1536]. Block tile 128x128, K-tile 32, 8 warps (4x2), warp 32x64.
// smem layout stride 36 words: frag lds conflict-free, STS.128 staging
// conflict-free (phase covers all 32 banks).
#define SST 36
__global__ __launch_bounds__(256) void gemm_gx_tc(
    const float* __restrict__ src,
    const float* __restrict__ Wih_f, const float* __restrict__ Wih_b,
    const float* __restrict__ bih_f, const float* __restrict__ bih_b)
{
    extern __shared__ unsigned sm_u[];
    unsigned* Ah = sm_u;                 // [128][36]
    unsigned* Al = Ah + 128 * SST;
    unsigned* Bh = Al + 128 * SST;
    unsigned* Bl = Bh + 128 * SST;

    const int m0 = blockIdx.x * 128;
    const int n0 = blockIdx.y * 128;     // tiles never straddle 768
    const bool fwd = (n0 < NG);
    const float* Bmat = fwd ? (Wih_f + (size_t)n0 * NI) : (Wih_b + (size_t)(n0 - NG) * NI);
    const float* bias = fwd ? (bih_f + n0) : (bih_b + (n0 - NG));
    float* outp = fwd ? g_gx_f : g_gx_b;
    const int nc0 = fwd ? n0 : (n0 - NG);

    const int tid = threadIdx.x;
    const int lane = tid & 31, warp = tid >> 5;
    const int wm = warp >> 1, wn = warp & 1;       // warp tile (wm*32, wn*64)
    const int grp = lane >> 2, tig = lane & 3;

    float acc[2][8][4];
#pragma unroll
    for (int s = 0; s < 2; s++)
#pragma unroll
        for (int ns = 0; ns < 8; ns++)
#pragma unroll
            for (int q = 0; q < 4; q++) acc[s][ns][q] = 0.f;

    // staging indices: l-th chunk -> idx = tid + l*256; row = idx>>3, kc=(idx&7)*4
    int srow[4], skc[4];
#pragma unroll
    for (int l = 0; l < 4; l++) { int idx = tid + l * 256; srow[l] = idx >> 3; skc[l] = (idx & 7) * 4; }

    float4 ra[4], rb[4];
#pragma unroll
    for (int l = 0; l < 4; l++) {
        ra[l] = *(const float4*)(src + (size_t)(m0 + srow[l]) * NI + skc[l]);
        rb[l] = *(const float4*)(Bmat + (size_t)srow[l] * NI + skc[l]);
    }

    for (int kt = 0; kt < NI / 32; kt++) {
        __syncthreads();
#pragma unroll
        for (int l = 0; l < 4; l++) {
            const int off = srow[l] * SST + skc[l];
            unsigned h0 = f2tf(ra[l].x), h1 = f2tf(ra[l].y), h2 = f2tf(ra[l].z), h3 = f2tf(ra[l].w);
            *(uint4*)(Ah + off) = make_uint4(h0, h1, h2, h3);
            *(uint4*)(Al + off) = make_uint4(
                f2tf(ra[l].x - __uint_as_float(h0)), f2tf(ra[l].y - __uint_as_float(h1)),
                f2tf(ra[l].z - __uint_as_float(h2)), f2tf(ra[l].w - __uint_as_float(h3)));
            unsigned g0 = f2tf(rb[l].x), g1 = f2tf(rb[l].y), g2 = f2tf(rb[l].z), g3 = f2tf(rb[l].w);
            *(uint4*)(Bh + off) = make_uint4(g0, g1, g2, g3);
            *(uint4*)(Bl + off) = make_uint4(
                f2tf(rb[l].x - __uint_as_float(g0)), f2tf(rb[l].y - __uint_as_float(g1)),
                f2tf(rb[l].z - __uint_as_float(g2)), f2tf(rb[l].w - __uint_as_float(g3)));
        }
        __syncthreads();
        if (kt + 1 < NI / 32) {
            const int k0 = (kt + 1) * 32;
#pragma unroll
            for (int l = 0; l < 4; l++) {
                ra[l] = *(const float4*)(src + (size_t)(m0 + srow[l]) * NI + k0 + skc[l]);
                rb[l] = *(const float4*)(Bmat + (size_t)srow[l] * NI + k0 + skc[l]);
            }
        }
#pragma unroll
        for (int kk = 0; kk < 4; kk++) {
            const int kb = kk * 8 + tig;
            unsigned ah[2][4], al[2][4];
#pragma unroll
            for (int s = 0; s < 2; s++) {
                const int r = wm * 32 + s * 16 + grp;
                ah[s][0] = Ah[r * SST + kb];       ah[s][1] = Ah[(r + 8) * SST + kb];
                ah[s][2] = Ah[r * SST + kb + 4];   ah[s][3] = Ah[(r + 8) * SST + kb + 4];
                al[s][0] = Al[r * SST + kb];       al[s][1] = Al[(r + 8) * SST + kb];
                al[s][2] = Al[r * SST + kb + 4];   al[s][3] = Al[(r + 8) * SST + kb + 4];
            }
#pragma unroll
            for (int ns = 0; ns < 8; ns++) {
                const int n = wn * 64 + ns * 8 + grp;
                const unsigned bh0 = Bh[n * SST + kb], bh1 = Bh[n * SST + kb + 4];
                const unsigned bl0 = Bl[n * SST + kb], bl1 = Bl[n * SST + kb + 4];
#pragma unroll
                for (int s = 0; s < 2; s++) {
                    MMA_TF32(acc[s][ns], ah[s], bh0, bh1);
                    MMA_TF32(acc[s][ns], ah[s], bl0, bl1);
                    MMA_TF32(acc[s][ns], al[s], bh0, bh1);
                }
            }
        }
    }

    // epilogue: C row = m0 + wm*32 + s*16 + grp (+8), col = wn*64 + ns*8 + tig*2
#pragma unroll
    for (int ns = 0; ns < 8; ns++) {
        const int cl = wn * 64 + ns * 8 + tig * 2;
        const float b0 = bias[cl], b1 = bias[cl + 1];
#pragma unroll
        for (int s = 0; s < 2; s++) {
            const int r = m0 + wm * 32 + s * 16 + grp;
            float* p0 = outp + (size_t)r * NG + nc0 + cl;
            float* p1 = outp + (size_t)(r + 8) * NG + nc0 + cl;
            *(float2*)p0 = make_float2(acc[s][ns][0] + b0, acc[s][ns][1] + b1);
            *(float2*)p1 = make_float2(acc[s][ns][2] + b0, acc[s][ns][3] + b1);
        }
    }
}

// ---------------- Kernel 2: persistent bidirectional GRU recurrence ---------
__global__ __launch_bounds__(256) void gru_rec_kernel(
    const float* __restrict__ Whh_f, const float* __restrict__ bhh_f,
    const float* __restrict__ Whh_b, const float* __restrict__ bhh_b)
{
    extern __shared__ float sm[];
    float* hs  = sm;                    // [64][260]  h_prev, padded rows
    float* ws  = sm + 64 * 260;         // [12][260]  Whh slice
    float* red = ws + 12 * 260;         // [8][32][24] k-split partials
    float* bs  = red + 8 * 32 * 24;     // [12] bhh slice (+pad)

    const int cta = blockIdx.x;
    const int tid = threadIdx.x;
    const int dir = cta >> 6;                // 0 fwd, 1 bwd
    const int j0  = (cta & 63) * 4;          // this CTA's h columns
    const float* Whh = dir ? Whh_b : Whh_f;
    const float* bhh = dir ? bhh_b : bhh_f;
    const float* gx  = dir ? g_gx_b : g_gx_f;
    float* out = dir ? g_out_b : g_out_f;

    for (int idx = tid; idx < 12 * 256; idx += 256) {
        int c = idx >> 8, k = idx & 255;
        int gc = (c >> 2) * NH + j0 + (c & 3);
        ws[c * 260 + k] = Whh[(size_t)gc * NH + k];
    }
    if (tid < 12) bs[tid] = bhh[(tid >> 2) * NH + j0 + (tid & 3)];

    const int kg = tid >> 5, lane = tid & 31;
    const int bq = lane & 7, cq = lane >> 3;
    const int kb = kg * 32;
    const int gb = tid >> 2, gj = tid & 3;
    __syncthreads();

    for (int s = 0; s < NT; s++) {
        const int t = dir ? (NT - 1 - s) : s;
        if (s == 0) {
            for (int i = tid; i < 64 * 260; i += 256) hs[i] = 0.f;
        } else {
            const int tp = dir ? (t + 1) : (t - 1);
            const float4* hp = (const float4*)(out + (size_t)tp * NB * NH);
            for (int i = tid; i < NB * NH / 4; i += 256) {
                float4 v = __ldcg(hp + i);
                const int b = i >> 6, k4 = (i & 63) * 4;
                float* d = hs + b * 260 + k4;
                d[0] = v.x; d[1] = v.y; d[2] = v.z; d[3] = v.w;
            }
        }
        __syncthreads();

        float acc[8][3];
#pragma unroll
        for (int i = 0; i < 8; i++) { acc[i][0] = 0.f; acc[i][1] = 0.f; acc[i][2] = 0.f; }
        const float* w0 = ws + (cq * 3 + 0) * 260;
        const float* w1 = ws + (cq * 3 + 1) * 260;
        const float* w2 = ws + (cq * 3 + 2) * 260;
#pragma unroll 4
        for (int k = kb; k < kb + 32; k++) {
            const float f0 = w0[k], f1 = w1[k], f2 = w2[k];
#pragma unroll
            for (int i = 0; i < 8; i++) {
                const float h = hs[(i * 8 + bq) * 260 + k];
                acc[i][0] += h * f0; acc[i][1] += h * f1; acc[i][2] += h * f2;
            }
        }
        float* rp = red + kg * 768 + lane * 24;
#pragma unroll
        for (int i = 0; i < 8; i++) {
            rp[i * 3 + 0] = acc[i][0]; rp[i * 3 + 1] = acc[i][1]; rp[i * 3 + 2] = acc[i][2];
        }
        __syncthreads();

        float gh[3];
#pragma unroll
        for (int g = 0; g < 3; g++) {
            const int c = g * 4 + gj;
            const int lane2 = (gb & 7) + (c / 3) * 8;
            const int oidx  = (gb >> 3) * 3 + (c % 3);
            float ssum = 0.f;
#pragma unroll
            for (int q = 0; q < 8; q++) ssum += red[q * 768 + lane2 * 24 + oidx];
            gh[g] = ssum + bs[c];
        }
        const float* gp = gx + ((size_t)t * NB + gb) * NG + j0 + gj;
        const float xr = gp[0], xz = gp[NH], xn = gp[2 * NH];
        const float r = 1.f / (1.f + expf(-(xr + gh[0])));
        const float z = 1.f / (1.f + expf(-(xz + gh[1])));
        const float n = tanhf(xn + r * gh[2]);
        const float hprev = hs[gb * 260 + j0 + gj];
        const float hnew = (1.f - z) * n + z * hprev;
        out[((size_t)t * NB + gb) * NH + j0 + gj] = hnew;

        __threadfence();
        __syncthreads();
        if (tid == 0) ((volatile unsigned*)g_flags)[cta * 32] = (unsigned)(s + 1);
        if (tid < 128) {
            const unsigned tgt = (unsigned)(s + 1);
            while (((volatile unsigned*)g_flags)[tid * 32] < tgt) __nanosleep(32);
        }
        __syncthreads();
    }
}

// ---------------- Kernel 3: outputs = [out_f|out_b] @ Wout^T + bout ---------
__global__ __launch_bounds__(256) void gemm_proj_kernel(
    const float* __restrict__ Wout, const float* __restrict__ bout,
    float* __restrict__ dst)
{
    __shared__ float As[16][128];
    __shared__ float Bs[16][128];
    const int m0 = blockIdx.x * 128;
    const int n0 = blockIdx.y * 128;
    const int tid = threadIdx.x;
    const int tx = tid & 15, ty = tid >> 4;

    float acc[8][8];
#pragma unroll
    for (int i = 0; i < 8; i++)
#pragma unroll
        for (int j = 0; j < 8; j++) acc[i][j] = 0.f;

    for (int k0 = 0; k0 < 512; k0 += 16) {
        const float* Asrc = (k0 < 256) ? g_out_f : g_out_b;
        const int kk0 = (k0 < 256) ? k0 : (k0 - 256);
#pragma unroll
        for (int i = 0; i < 2; i++) {
            int f = tid * 2 + i;
            int row = f >> 2, kc = (f & 3) * 4;
            float4 v = *(const float4*)(Asrc + (size_t)(m0 + row) * NH + kk0 + kc);
            As[kc][row] = v.x; As[kc + 1][row] = v.y; As[kc + 2][row] = v.z; As[kc + 3][row] = v.w;
            float4 w = *(const float4*)(Wout + (size_t)(n0 + row) * 512 + k0 + kc);
            Bs[kc][row] = w.x; Bs[kc + 1][row] = w.y; Bs[kc + 2][row] = w.z; Bs[kc + 3][row] = w.w;
        }
        __syncthreads();
#pragma unroll
        for (int k = 0; k < 16; k++) {
            float a[8], b[8];
            *(float4*)&a[0] = *(const float4*)&As[k][ty * 8];
            *(float4*)&a[4] = *(const float4*)&As[k][ty * 8 + 4];
            *(float4*)&b[0] = *(const float4*)&Bs[k][tx * 8];
            *(float4*)&b[4] = *(const float4*)&Bs[k][tx * 8 + 4];
#pragma unroll
            for (int i = 0; i < 8; i++)
#pragma unroll
                for (int j = 0; j < 8; j++) acc[i][j] += a[i] * b[j];
        }
        __syncthreads();
    }
    float bv[8];
#pragma unroll
    for (int j = 0; j < 8; j++) bv[j] = bout[n0 + tx * 8 + j];
#pragma unroll
    for (int i = 0; i < 8; i++) {
        const int m = m0 + ty * 8 + i;
        float4 o0, o1;
        o0.x = acc[i][0] + bv[0]; o0.y = acc[i][1] + bv[1];
        o0.z = acc[i][2] + bv[2]; o0.w = acc[i][3] + bv[3];
        o1.x = acc[i][4] + bv[4]; o1.y = acc[i][5] + bv[5];
        o1.z = acc[i][6] + bv[6]; o1.w = acc[i][7] + bv[7];
        float* op = dst + (size_t)m * NH + n0 + tx * 8;
        *(float4*)op = o0;
        *(float4*)(op + 4) = o1;
    }
}

// ---------------- Kernel 4: hidden = tanh([h_f|h_b] @ Whid^T + bhid) --------
__global__ __launch_bounds__(256) void hidden_kernel(
    const float* __restrict__ Whid, const float* __restrict__ bhid,
    float* __restrict__ outh)
{
    __shared__ float hc[512];
    const int b = blockIdx.x, tid = threadIdx.x;
    hc[tid]       = g_out_f[((size_t)(NT - 1) * NB + b) * NH + tid];
    hc[256 + tid] = g_out_b[((size_t)b) * NH + tid];
    __syncthreads();
    const float* w = Whid + (size_t)tid * 512;
    float ssum = bhid[tid];
#pragma unroll 8
    for (int k = 0; k < 512; k++) ssum += hc[k] * w[k];
    outh[(size_t)b * NH + tid] = tanhf(ssum);
}

// ---------------- launcher ---------------------------------------------------
extern "C" void kernel_launch(void* const* d_in, const int* in_sizes, int n_in,
                              void* d_out, int out_size)
{
    const float* src   = (const float*)d_in[0];
    const float* Wih_f = (const float*)d_in[1];
    const float* Whh_f = (const float*)d_in[2];
    const float* bih_f = (const float*)d_in[3];
    const float* bhh_f = (const float*)d_in[4];
    const float* Wih_b = (const float*)d_in[5];
    const float* Whh_b = (const float*)d_in[6];
    const float* bih_b = (const float*)d_in[7];
    const float* bhh_b = (const float*)d_in[8];
    const float* Wout  = (const float*)d_in[9];
    const float* bout  = (const float*)d_in[10];
    const float* Whid  = (const float*)d_in[11];
    const float* bhid  = (const float*)d_in[12];
    float* out = (float*)d_out;

    const int gx_smem = 4 * 128 * SST * (int)sizeof(unsigned);   // 73728
    cudaFuncSetAttribute(gemm_gx_tc,
                         cudaFuncAttributeMaxDynamicSharedMemorySize, gx_smem);
    const int rec_smem = (64 * 260 + 12 * 260 + 8 * 32 * 24 + 16) * (int)sizeof(float);
    cudaFuncSetAttribute(gru_rec_kernel,
                         cudaFuncAttributeMaxDynamicSharedMemorySize, rec_smem);

    init_flags_kernel<<<1, 128>>>();
    gemm_gx_tc<<<dim3(256, 12), 256, gx_smem>>>(src, Wih_f, Wih_b, bih_f, bih_b);
    gru_rec_kernel<<<128, 256, rec_smem>>>(Whh_f, bhh_f, Whh_b, bhh_b);
    gemm_proj_kernel<<<dim3(256, 2), 256>>>(Wout, bout, out);
    hidden_kernel<<<64, 256>>>(Whid, bhid, out + (size_t)NT * NB * NH);
}

// round 3
// speedup vs baseline: 1.4447x; 1.2314x over previous
#include <cuda_runtime.h>
#include <cuda_bf16.h>
#include <math.h>

#define NT 512
#define NB 64
#define NI 1024
#define NH 256
#define NG 768   // 3*NH

// ---------------- scratch (device globals: no allocations allowed) ----------
__device__ float g_gx_f[NT * NB * NG];   // 100.7 MB
__device__ float g_gx_b[NT * NB * NG];   // 100.7 MB
__device__ float g_out_f[NT * NB * NH];  // 33.6 MB : fwd hidden history
__device__ float g_out_b[NT * NB * NH];  // 33.6 MB : bwd hidden history
__device__ unsigned g_flags[128 * 32];   // grid-barrier flags, 128B apart

__global__ void init_flags_kernel() {
    if (threadIdx.x < 128)
        ((volatile unsigned*)g_flags)[threadIdx.x * 32] = 0u;
}

// ---------------- bf16 helpers ----------------------------------------------
// Split (x,y) into packed-bf16 hi pair and packed-bf16 residual pair.
__device__ __forceinline__ void bfsplit(float x, float y, unsigned& hi, unsigned& lo) {
    unsigned short bx = __bfloat16_as_ushort(__float2bfloat16_rn(x));
    unsigned short by = __bfloat16_as_ushort(__float2bfloat16_rn(y));
    hi = (unsigned)bx | ((unsigned)by << 16);
    float fx = __uint_as_float((unsigned)bx << 16);
    float fy = __uint_as_float((unsigned)by << 16);
    __nv_bfloat162 t = __floats2bfloat162_rn(x - fx, y - fy);
    lo = reinterpret_cast<unsigned&>(t);
}

#define MMA_BF16(d, a, b0, b1)                                                  \
    asm volatile("mma.sync.aligned.m16n8k16.row.col.f32.bf16.bf16.f32 "         \
        "{%0,%1,%2,%3}, {%4,%5,%6,%7}, {%8,%9}, {%0,%1,%2,%3};"                 \
        : "+f"(d[0]), "+f"(d[1]), "+f"(d[2]), "+f"(d[3])                        \
        : "r"(a[0]), "r"(a[1]), "r"(a[2]), "r"(a[3]), "r"(b0), "r"(b1))

#define FMA_F32X2(d, a, b)                                                      \
    asm("fma.rn.f32x2 %0, %1, %2, %0;" : "+l"(d) : "l"(a), "l"(b))

// ---------------- Kernel 1: gx = src @ Wih^T + bih (bf16x3 tensor cores) ----
// C[32768 x 1536]. Block tile 128x128, K-tile 32, 8 warps (4x2), warp 32x64.
// Planes Ah/Al/Bh/Bl: [128 rows][16 kpairs] u32, row stride 20 (conflict-free
// fragment loads: grp*20 mod 32 covers 8 banks spaced >=4 apart).
#define SST2 20
__global__ __launch_bounds__(256, 2) void gemm_gx_tc(
    const float* __restrict__ src,
    const float* __restrict__ Wih_f, const float* __restrict__ Wih_b,
    const float* __restrict__ bih_f, const float* __restrict__ bih_b)
{
    extern __shared__ unsigned sm_u[];
    unsigned* Ah = sm_u;                 // [128][20]
    unsigned* Al = Ah + 128 * SST2;
    unsigned* Bh = Al + 128 * SST2;
    unsigned* Bl = Bh + 128 * SST2;

    const int m0 = blockIdx.x * 128;
    const int n0 = blockIdx.y * 128;     // tiles never straddle 768
    const bool fwd = (n0 < NG);
    const float* Bmat = fwd ? (Wih_f + (size_t)n0 * NI) : (Wih_b + (size_t)(n0 - NG) * NI);
    const float* bias = fwd ? (bih_f + n0) : (bih_b + (n0 - NG));
    float* outp = fwd ? g_gx_f : g_gx_b;
    const int nc0 = fwd ? n0 : (n0 - NG);

    const int tid = threadIdx.x;
    const int lane = tid & 31, warp = tid >> 5;
    const int wm = warp >> 1, wn = warp & 1;       // warp tile (wm*32, wn*64)
    const int grp = lane >> 2, tig = lane & 3;

    float acc[2][8][4];
#pragma unroll
    for (int s = 0; s < 2; s++)
#pragma unroll
        for (int ns = 0; ns < 8; ns++)
#pragma unroll
            for (int q = 0; q < 4; q++) acc[s][ns][q] = 0.f;

    int srow[4], skc[4];
#pragma unroll
    for (int l = 0; l < 4; l++) { int idx = tid + l * 256; srow[l] = idx >> 3; skc[l] = (idx & 7) * 4; }

    float4 ra[4], rb[4];
#pragma unroll
    for (int l = 0; l < 4; l++) {
        ra[l] = *(const float4*)(src + (size_t)(m0 + srow[l]) * NI + skc[l]);
        rb[l] = *(const float4*)(Bmat + (size_t)srow[l] * NI + skc[l]);
    }

    for (int kt = 0; kt < NI / 32; kt++) {
        __syncthreads();
#pragma unroll
        for (int l = 0; l < 4; l++) {
            const int off = srow[l] * SST2 + (skc[l] >> 1);
            unsigned h0, h1, l0, l1;
            bfsplit(ra[l].x, ra[l].y, h0, l0);
            bfsplit(ra[l].z, ra[l].w, h1, l1);
            *(uint2*)(Ah + off) = make_uint2(h0, h1);
            *(uint2*)(Al + off) = make_uint2(l0, l1);
            bfsplit(rb[l].x, rb[l].y, h0, l0);
            bfsplit(rb[l].z, rb[l].w, h1, l1);
            *(uint2*)(Bh + off) = make_uint2(h0, h1);
            *(uint2*)(Bl + off) = make_uint2(l0, l1);
        }
        __syncthreads();
        if (kt + 1 < NI / 32) {
            const int k0 = (kt + 1) * 32;
#pragma unroll
            for (int l = 0; l < 4; l++) {
                ra[l] = *(const float4*)(src + (size_t)(m0 + srow[l]) * NI + k0 + skc[l]);
                rb[l] = *(const float4*)(Bmat + (size_t)srow[l] * NI + k0 + skc[l]);
            }
        }
#pragma unroll
        for (int kk = 0; kk < 2; kk++) {
            unsigned ah[2][4], al[2][4];
#pragma unroll
            for (int s = 0; s < 2; s++) {
                const int r = wm * 32 + s * 16 + grp;
                const int base = r * SST2 + kk * 8 + tig;
                ah[s][0] = Ah[base];            ah[s][1] = Ah[base + 8 * SST2];
                ah[s][2] = Ah[base + 4];        ah[s][3] = Ah[base + 8 * SST2 + 4];
                al[s][0] = Al[base];            al[s][1] = Al[base + 8 * SST2];
                al[s][2] = Al[base + 4];        al[s][3] = Al[base + 8 * SST2 + 4];
            }
#pragma unroll
            for (int ns = 0; ns < 8; ns++) {
                const int n = wn * 64 + ns * 8 + grp;
                const int nb = n * SST2 + kk * 8 + tig;
                const unsigned bh0 = Bh[nb], bh1 = Bh[nb + 4];
                const unsigned bl0 = Bl[nb], bl1 = Bl[nb + 4];
#pragma unroll
                for (int s = 0; s < 2; s++) {
                    MMA_BF16(acc[s][ns], ah[s], bh0, bh1);
                    MMA_BF16(acc[s][ns], al[s], bh0, bh1);
                    MMA_BF16(acc[s][ns], ah[s], bl0, bl1);
                }
            }
        }
    }

#pragma unroll
    for (int ns = 0; ns < 8; ns++) {
        const int cl = wn * 64 + ns * 8 + tig * 2;
        const float b0 = bias[cl], b1 = bias[cl + 1];
#pragma unroll
        for (int s = 0; s < 2; s++) {
            const int r = m0 + wm * 32 + s * 16 + grp;
            float* p0 = outp + (size_t)r * NG + nc0 + cl;
            float* p1 = outp + (size_t)(r + 8) * NG + nc0 + cl;
            *(float2*)p0 = make_float2(acc[s][ns][0] + b0, acc[s][ns][1] + b1);
            *(float2*)p1 = make_float2(acc[s][ns][2] + b0, acc[s][ns][3] + b1);
        }
    }
}

// ---------------- Kernel 2: persistent bidirectional GRU recurrence ---------
// FFMA2 (fma.rn.f32x2) inner loop: 2 k per FMA instruction, LDS.64 operand loads.
__global__ __launch_bounds__(256) void gru_rec_kernel(
    const float* __restrict__ Whh_f, const float* __restrict__ bhh_f,
    const float* __restrict__ Whh_b, const float* __restrict__ bhh_b)
{
    extern __shared__ float sm[];
    float* hs  = sm;                    // [64][260]  h_prev, padded rows
    float* ws  = sm + 64 * 260;         // [12][260]  Whh slice
    float* red = ws + 12 * 260;         // [8][32][24] k-split partials
    float* bs  = red + 8 * 32 * 24;     // [12] bhh slice (+pad)

    const int cta = blockIdx.x;
    const int tid = threadIdx.x;
    const int dir = cta >> 6;                // 0 fwd, 1 bwd
    const int j0  = (cta & 63) * 4;          // this CTA's h columns
    const float* Whh = dir ? Whh_b : Whh_f;
    const float* bhh = dir ? bhh_b : bhh_f;
    const float* gx  = dir ? g_gx_b : g_gx_f;
    float* out = dir ? g_out_b : g_out_f;

    for (int idx = tid; idx < 12 * 256; idx += 256) {
        int c = idx >> 8, k = idx & 255;
        int gc = (c >> 2) * NH + j0 + (c & 3);
        ws[c * 260 + k] = Whh[(size_t)gc * NH + k];
    }
    if (tid < 12) bs[tid] = bhh[(tid >> 2) * NH + j0 + (tid & 3)];

    const int kg = tid >> 5, lane = tid & 31;
    const int bq = lane & 7, cq = lane >> 3;
    const int kb = kg * 32;
    const int gb = tid >> 2, gj = tid & 3;
    __syncthreads();

    for (int s = 0; s < NT; s++) {
        const int t = dir ? (NT - 1 - s) : s;
        if (s == 0) {
            for (int i = tid; i < 64 * 260; i += 256) hs[i] = 0.f;
        } else {
            const int tp = dir ? (t + 1) : (t - 1);
            const float4* hp = (const float4*)(out + (size_t)tp * NB * NH);
            for (int i = tid; i < NB * NH / 4; i += 256) {
                float4 v = __ldcg(hp + i);
                const int b = i >> 6, k4 = (i & 63) * 4;
                float* d = hs + b * 260 + k4;
                d[0] = v.x; d[1] = v.y; d[2] = v.z; d[3] = v.w;
            }
        }
        __syncthreads();

        // gh partials: packed f32x2 over k pairs
        unsigned long long acc2[8][3];
#pragma unroll
        for (int i = 0; i < 8; i++) { acc2[i][0] = 0ull; acc2[i][1] = 0ull; acc2[i][2] = 0ull; }
        const unsigned long long* w0p = (const unsigned long long*)(ws + (cq * 3 + 0) * 260 + kb);
        const unsigned long long* w1p = (const unsigned long long*)(ws + (cq * 3 + 1) * 260 + kb);
        const unsigned long long* w2p = (const unsigned long long*)(ws + (cq * 3 + 2) * 260 + kb);
#pragma unroll 4
        for (int kp = 0; kp < 16; kp++) {
            const unsigned long long f0 = w0p[kp], f1 = w1p[kp], f2 = w2p[kp];
#pragma unroll
            for (int i = 0; i < 8; i++) {
                const unsigned long long h2 =
                    *(const unsigned long long*)(hs + (i * 8 + bq) * 260 + kb + kp * 2);
                FMA_F32X2(acc2[i][0], h2, f0);
                FMA_F32X2(acc2[i][1], h2, f1);
                FMA_F32X2(acc2[i][2], h2, f2);
            }
        }
        float* rp = red + kg * 768 + lane * 24;
#pragma unroll
        for (int i = 0; i < 8; i++) {
#pragma unroll
            for (int c = 0; c < 3; c++) {
                const unsigned long long a = acc2[i][c];
                rp[i * 3 + c] = __uint_as_float((unsigned)a) +
                                __uint_as_float((unsigned)(a >> 32));
            }
        }
        __syncthreads();

        float gh[3];
#pragma unroll
        for (int g = 0; g < 3; g++) {
            const int c = g * 4 + gj;
            const int lane2 = (gb & 7) + (c / 3) * 8;
            const int oidx  = (gb >> 3) * 3 + (c % 3);
            float ssum = 0.f;
#pragma unroll
            for (int q = 0; q < 8; q++) ssum += red[q * 768 + lane2 * 24 + oidx];
            gh[g] = ssum + bs[c];
        }
        const float* gp = gx + ((size_t)t * NB + gb) * NG + j0 + gj;
        const float xr = gp[0], xz = gp[NH], xn = gp[2 * NH];
        const float r = 1.f / (1.f + expf(-(xr + gh[0])));
        const float z = 1.f / (1.f + expf(-(xz + gh[1])));
        const float n = tanhf(xn + r * gh[2]);
        const float hprev = hs[gb * 260 + j0 + gj];
        const float hnew = (1.f - z) * n + z * hprev;
        out[((size_t)t * NB + gb) * NH + j0 + gj] = hnew;

        __threadfence();
        __syncthreads();
        if (tid == 0) ((volatile unsigned*)g_flags)[cta * 32] = (unsigned)(s + 1);
        if (tid < 128) {
            const unsigned tgt = (unsigned)(s + 1);
            while (((volatile unsigned*)g_flags)[tid * 32] < tgt) __nanosleep(32);
        }
        __syncthreads();
    }
}

// ---------------- Kernel 3: outputs = [out_f|out_b] @ Wout^T + bout (bf16x3) -
__global__ __launch_bounds__(256, 2) void gemm_proj_tc(
    const float* __restrict__ Wout, const float* __restrict__ bout,
    float* __restrict__ dst)
{
    extern __shared__ unsigned sm_u[];
    unsigned* Ah = sm_u;
    unsigned* Al = Ah + 128 * SST2;
    unsigned* Bh = Al + 128 * SST2;
    unsigned* Bl = Bh + 128 * SST2;

    const int m0 = blockIdx.x * 128;
    const int n0 = blockIdx.y * 128;       // 0 or 128
    const int tid = threadIdx.x;
    const int lane = tid & 31, warp = tid >> 5;
    const int wm = warp >> 1, wn = warp & 1;
    const int grp = lane >> 2, tig = lane & 3;

    float acc[2][8][4];
#pragma unroll
    for (int s = 0; s < 2; s++)
#pragma unroll
        for (int ns = 0; ns < 8; ns++)
#pragma unroll
            for (int q = 0; q < 4; q++) acc[s][ns][q] = 0.f;

    int srow[4], skc[4];
#pragma unroll
    for (int l = 0; l < 4; l++) { int idx = tid + l * 256; srow[l] = idx >> 3; skc[l] = (idx & 7) * 4; }

    float4 ra[4], rb[4];
#pragma unroll
    for (int l = 0; l < 4; l++) {
        ra[l] = *(const float4*)(g_out_f + (size_t)(m0 + srow[l]) * NH + skc[l]);
        rb[l] = *(const float4*)(Wout + (size_t)(n0 + srow[l]) * 512 + skc[l]);
    }

    for (int kt = 0; kt < 16; kt++) {
        __syncthreads();
#pragma unroll
        for (int l = 0; l < 4; l++) {
            const int off = srow[l] * SST2 + (skc[l] >> 1);
            unsigned h0, h1, l0, l1;
            bfsplit(ra[l].x, ra[l].y, h0, l0);
            bfsplit(ra[l].z, ra[l].w, h1, l1);
            *(uint2*)(Ah + off) = make_uint2(h0, h1);
            *(uint2*)(Al + off) = make_uint2(l0, l1);
            bfsplit(rb[l].x, rb[l].y, h0, l0);
            bfsplit(rb[l].z, rb[l].w, h1, l1);
            *(uint2*)(Bh + off) = make_uint2(h0, h1);
            *(uint2*)(Bl + off) = make_uint2(l0, l1);
        }
        __syncthreads();
        if (kt + 1 < 16) {
            const int k0 = (kt + 1) * 32;
            const float* Asrc = (k0 < 256) ? g_out_f : g_out_b;
            const int kk0 = k0 & 255;
#pragma unroll
            for (int l = 0; l < 4; l++) {
                ra[l] = *(const float4*)(Asrc + (size_t)(m0 + srow[l]) * NH + kk0 + skc[l]);
                rb[l] = *(const float4*)(Wout + (size_t)(n0 + srow[l]) * 512 + k0 + skc[l]);
            }
        }
#pragma unroll
        for (int kk = 0; kk < 2; kk++) {
            unsigned ah[2][4], al[2][4];
#pragma unroll
            for (int s = 0; s < 2; s++) {
                const int r = wm * 32 + s * 16 + grp;
                const int base = r * SST2 + kk * 8 + tig;
                ah[s][0] = Ah[base];            ah[s][1] = Ah[base + 8 * SST2];
                ah[s][2] = Ah[base + 4];        ah[s][3] = Ah[base + 8 * SST2 + 4];
                al[s][0] = Al[base];            al[s][1] = Al[base + 8 * SST2];
                al[s][2] = Al[base + 4];        al[s][3] = Al[base + 8 * SST2 + 4];
            }
#pragma unroll
            for (int ns = 0; ns < 8; ns++) {
                const int n = wn * 64 + ns * 8 + grp;
                const int nb = n * SST2 + kk * 8 + tig;
                const unsigned bh0 = Bh[nb], bh1 = Bh[nb + 4];
                const unsigned bl0 = Bl[nb], bl1 = Bl[nb + 4];
#pragma unroll
                for (int s = 0; s < 2; s++) {
                    MMA_BF16(acc[s][ns], ah[s], bh0, bh1);
                    MMA_BF16(acc[s][ns], al[s], bh0, bh1);
                    MMA_BF16(acc[s][ns], ah[s], bl0, bl1);
                }
            }
        }
    }

#pragma unroll
    for (int ns = 0; ns < 8; ns++) {
        const int cl = wn * 64 + ns * 8 + tig * 2;
        const float b0 = bout[n0 + cl], b1 = bout[n0 + cl + 1];
#pragma unroll
        for (int s = 0; s < 2; s++) {
            const int r = m0 + wm * 32 + s * 16 + grp;
            float* p0 = dst + (size_t)r * NH + n0 + cl;
            float* p1 = dst + (size_t)(r + 8) * NH + n0 + cl;
            *(float2*)p0 = make_float2(acc[s][ns][0] + b0, acc[s][ns][1] + b1);
            *(float2*)p1 = make_float2(acc[s][ns][2] + b0, acc[s][ns][3] + b1);
        }
    }
}

// ---------------- Kernel 4: hidden = tanh([h_f|h_b] @ Whid^T + bhid) --------
__global__ __launch_bounds__(256) void hidden_kernel(
    const float* __restrict__ Whid, const float* __restrict__ bhid,
    float* __restrict__ outh)
{
    __shared__ float hc[512];
    const int b = blockIdx.x, tid = threadIdx.x;
    hc[tid]       = g_out_f[((size_t)(NT - 1) * NB + b) * NH + tid];
    hc[256 + tid] = g_out_b[((size_t)b) * NH + tid];
    __syncthreads();
    const float* w = Whid + (size_t)tid * 512;
    float ssum = bhid[tid];
#pragma unroll 8
    for (int k = 0; k < 512; k++) ssum += hc[k] * w[k];
    outh[(size_t)b * NH + tid] = tanhf(ssum);
}

// ---------------- launcher ---------------------------------------------------
extern "C" void kernel_launch(void* const* d_in, const int* in_sizes, int n_in,
                              void* d_out, int out_size)
{
    const float* src   = (const float*)d_in[0];
    const float* Wih_f = (const float*)d_in[1];
    const float* Whh_f = (const float*)d_in[2];
    const float* bih_f = (const float*)d_in[3];
    const float* bhh_f = (const float*)d_in[4];
    const float* Wih_b = (const float*)d_in[5];
    const float* Whh_b = (const float*)d_in[6];
    const float* bih_b = (const float*)d_in[7];
    const float* bhh_b = (const float*)d_in[8];
    const float* Wout  = (const float*)d_in[9];
    const float* bout  = (const float*)d_in[10];
    const float* Whid  = (const float*)d_in[11];
    const float* bhid  = (const float*)d_in[12];
    float* out = (float*)d_out;

    const int gx_smem = 4 * 128 * SST2 * (int)sizeof(unsigned);  // 40960
    cudaFuncSetAttribute(gemm_gx_tc,
                         cudaFuncAttributeMaxDynamicSharedMemorySize, gx_smem);
    cudaFuncSetAttribute(gemm_proj_tc,
                         cudaFuncAttributeMaxDynamicSharedMemorySize, gx_smem);
    const int rec_smem = (64 * 260 + 12 * 260 + 8 * 32 * 24 + 16) * (int)sizeof(float);
    cudaFuncSetAttribute(gru_rec_kernel,
                         cudaFuncAttributeMaxDynamicSharedMemorySize, rec_smem);

    init_flags_kernel<<<1, 128>>>();
    gemm_gx_tc<<<dim3(256, 12), 256, gx_smem>>>(src, Wih_f, Wih_b, bih_f, bih_b);
    gru_rec_kernel<<<128, 256, rec_smem>>>(Whh_f, bhh_f, Whh_b, bhh_b);
    gemm_proj_tc<<<dim3(256, 2), 256, gx_smem>>>(Wout, bout, out);
    hidden_kernel<<<64, 256>>>(Whid, bhid, out + (size_t)NT * NB * NH);
}

// round 4
// speedup vs baseline: 1.5439x; 1.0687x over previous
#include <cuda_runtime.h>
#include <cuda_bf16.h>
#include <math.h>

#define NT 512
#define NB 64
#define NI 1024
#define NH 256
#define NG 768   // 3*NH

// ---------------- scratch (device globals: no allocations allowed) ----------
__device__ float g_gx_f[NT * NB * NG];   // 100.7 MB
__device__ float g_gx_b[NT * NB * NG];   // 100.7 MB
__device__ float g_out_f[NT * NB * NH];  // 33.6 MB : fwd hidden history
__device__ float g_out_b[NT * NB * NH];  // 33.6 MB : bwd hidden history
__device__ unsigned g_flags[128 * 32];   // grid-barrier flags, 128B apart

__global__ void init_flags_kernel() {
    if (threadIdx.x < 128)
        ((volatile unsigned*)g_flags)[threadIdx.x * 32] = 0u;
}

// ---------------- bf16 helpers ----------------------------------------------
__device__ __forceinline__ void bfsplit(float x, float y, unsigned& hi, unsigned& lo) {
    unsigned short bx = __bfloat16_as_ushort(__float2bfloat16_rn(x));
    unsigned short by = __bfloat16_as_ushort(__float2bfloat16_rn(y));
    hi = (unsigned)bx | ((unsigned)by << 16);
    float fx = __uint_as_float((unsigned)bx << 16);
    float fy = __uint_as_float((unsigned)by << 16);
    __nv_bfloat162 t = __floats2bfloat162_rn(x - fx, y - fy);
    lo = reinterpret_cast<unsigned&>(t);
}

#define MMA_BF16(d, a, b0, b1)                                                  \
    asm volatile("mma.sync.aligned.m16n8k16.row.col.f32.bf16.bf16.f32 "         \
        "{%0,%1,%2,%3}, {%4,%5,%6,%7}, {%8,%9}, {%0,%1,%2,%3};"                 \
        : "+f"(d[0]), "+f"(d[1]), "+f"(d[2]), "+f"(d[3])                        \
        : "r"(a[0]), "r"(a[1]), "r"(a[2]), "r"(a[3]), "r"(b0), "r"(b1))

#define LDSM_X4(r, addr)                                                        \
    asm volatile("ldmatrix.sync.aligned.m8n8.x4.shared.b16 {%0,%1,%2,%3}, [%4];"\
        : "=r"((r)[0]), "=r"((r)[1]), "=r"((r)[2]), "=r"((r)[3]) : "r"(addr))

__device__ __forceinline__ unsigned smem_u32(const void* p) {
    return (unsigned)__cvta_generic_to_shared(p);
}

// ---------------- Kernel 1: gx = src @ Wih^T + bih (bf16x3 tensor cores) ----
#define SST2 20
__global__ __launch_bounds__(256, 2) void gemm_gx_tc(
    const float* __restrict__ src,
    const float* __restrict__ Wih_f, const float* __restrict__ Wih_b,
    const float* __restrict__ bih_f, const float* __restrict__ bih_b)
{
    extern __shared__ unsigned sm_u[];
    unsigned* Ah = sm_u;                 // [128][20]
    unsigned* Al = Ah + 128 * SST2;
    unsigned* Bh = Al + 128 * SST2;
    unsigned* Bl = Bh + 128 * SST2;

    const int m0 = blockIdx.x * 128;
    const int n0 = blockIdx.y * 128;
    const bool fwd = (n0 < NG);
    const float* Bmat = fwd ? (Wih_f + (size_t)n0 * NI) : (Wih_b + (size_t)(n0 - NG) * NI);
    const float* bias = fwd ? (bih_f + n0) : (bih_b + (n0 - NG));
    float* outp = fwd ? g_gx_f : g_gx_b;
    const int nc0 = fwd ? n0 : (n0 - NG);

    const int tid = threadIdx.x;
    const int lane = tid & 31, warp = tid >> 5;
    const int wm = warp >> 1, wn = warp & 1;
    const int grp = lane >> 2, tig = lane & 3;

    float acc[2][8][4];
#pragma unroll
    for (int s = 0; s < 2; s++)
#pragma unroll
        for (int ns = 0; ns < 8; ns++)
#pragma unroll
            for (int q = 0; q < 4; q++) acc[s][ns][q] = 0.f;

    int srow[4], skc[4];
#pragma unroll
    for (int l = 0; l < 4; l++) { int idx = tid + l * 256; srow[l] = idx >> 3; skc[l] = (idx & 7) * 4; }

    float4 ra[4], rb[4];
#pragma unroll
    for (int l = 0; l < 4; l++) {
        ra[l] = *(const float4*)(src + (size_t)(m0 + srow[l]) * NI + skc[l]);
        rb[l] = *(const float4*)(Bmat + (size_t)srow[l] * NI + skc[l]);
    }

    for (int kt = 0; kt < NI / 32; kt++) {
        __syncthreads();
#pragma unroll
        for (int l = 0; l < 4; l++) {
            const int off = srow[l] * SST2 + (skc[l] >> 1);
            unsigned h0, h1, l0, l1;
            bfsplit(ra[l].x, ra[l].y, h0, l0);
            bfsplit(ra[l].z, ra[l].w, h1, l1);
            *(uint2*)(Ah + off) = make_uint2(h0, h1);
            *(uint2*)(Al + off) = make_uint2(l0, l1);
            bfsplit(rb[l].x, rb[l].y, h0, l0);
            bfsplit(rb[l].z, rb[l].w, h1, l1);
            *(uint2*)(Bh + off) = make_uint2(h0, h1);
            *(uint2*)(Bl + off) = make_uint2(l0, l1);
        }
        __syncthreads();
        if (kt + 1 < NI / 32) {
            const int k0 = (kt + 1) * 32;
#pragma unroll
            for (int l = 0; l < 4; l++) {
                ra[l] = *(const float4*)(src + (size_t)(m0 + srow[l]) * NI + k0 + skc[l]);
                rb[l] = *(const float4*)(Bmat + (size_t)srow[l] * NI + k0 + skc[l]);
            }
        }
#pragma unroll
        for (int kk = 0; kk < 2; kk++) {
            unsigned ah[2][4], al[2][4];
#pragma unroll
            for (int s = 0; s < 2; s++) {
                const int r = wm * 32 + s * 16 + grp;
                const int base = r * SST2 + kk * 8 + tig;
                ah[s][0] = Ah[base];            ah[s][1] = Ah[base + 8 * SST2];
                ah[s][2] = Ah[base + 4];        ah[s][3] = Ah[base + 8 * SST2 + 4];
                al[s][0] = Al[base];            al[s][1] = Al[base + 8 * SST2];
                al[s][2] = Al[base + 4];        al[s][3] = Al[base + 8 * SST2 + 4];
            }
#pragma unroll
            for (int ns = 0; ns < 8; ns++) {
                const int n = wn * 64 + ns * 8 + grp;
                const int nb = n * SST2 + kk * 8 + tig;
                const unsigned bh0 = Bh[nb], bh1 = Bh[nb + 4];
                const unsigned bl0 = Bl[nb], bl1 = Bl[nb + 4];
#pragma unroll
                for (int s = 0; s < 2; s++) {
                    MMA_BF16(acc[s][ns], ah[s], bh0, bh1);
                    MMA_BF16(acc[s][ns], al[s], bh0, bh1);
                    MMA_BF16(acc[s][ns], ah[s], bl0, bl1);
                }
            }
        }
    }

#pragma unroll
    for (int ns = 0; ns < 8; ns++) {
        const int cl = wn * 64 + ns * 8 + tig * 2;
        const float b0 = bias[cl], b1 = bias[cl + 1];
#pragma unroll
        for (int s = 0; s < 2; s++) {
            const int r = m0 + wm * 32 + s * 16 + grp;
            float* p0 = outp + (size_t)r * NG + nc0 + cl;
            float* p1 = outp + (size_t)(r + 8) * NG + nc0 + cl;
            *(float2*)p0 = make_float2(acc[s][ns][0] + b0, acc[s][ns][1] + b1);
            *(float2*)p1 = make_float2(acc[s][ns][2] + b0, acc[s][ns][3] + b1);
        }
    }
}

// ---------------- Kernel 2: persistent GRU recurrence on tensor cores -------
// 128 CTAs (64/dir), CTA owns 4 h-cols = 12 gate cols (padded to 16).
// Per step: gh = h[64x256] @ WhhSlice^T via mma bf16x3; Whh frags preloaded
// in registers for all 512 steps; h staged to bf16 hi/lo smem planes.
__global__ __launch_bounds__(256) void gru_rec_tc(
    const float* __restrict__ Whh_f, const float* __restrict__ bhh_f,
    const float* __restrict__ Whh_b, const float* __restrict__ bhh_b)
{
    extern __shared__ unsigned smu[];
    unsigned* hsH = smu;                      // [64][132]
    unsigned* hsL = hsH + 64 * 132;           // [64][132]
    unsigned* whH = hsL + 64 * 132;           // [16][132]
    unsigned* whL = whH + 16 * 132;           // [16][132]
    float*    red = (float*)(whL + 16 * 132); // [16][68]
    float*    bsm = red + 16 * 68;            // [12]

    const int cta = blockIdx.x;
    const int tid = threadIdx.x;
    const int dir = cta >> 6;
    const int j0  = (cta & 63) * 4;
    const float* Whh = dir ? Whh_b : Whh_f;
    const float* bhh = dir ? bhh_b : bhh_f;
    const float* gx  = dir ? g_gx_b : g_gx_f;
    float* out = dir ? g_out_b : g_out_f;

    // Whh slice -> bf16 hi/lo planes (rows 12..15 zero padding)
    for (int idx = tid; idx < 16 * 128; idx += 256) {
        const int row = idx >> 7, col = idx & 127;
        unsigned hi = 0u, lo = 0u;
        if (row < 12) {
            const float* wr = Whh + (size_t)((row >> 2) * NH + j0 + (row & 3)) * NH + col * 2;
            bfsplit(wr[0], wr[1], hi, lo);
        }
        whH[row * 132 + col] = hi;
        whL[row * 132 + col] = lo;
    }
    if (tid < 12) bsm[tid] = bhh[(tid >> 2) * NH + j0 + (tid & 3)];
    for (int i = tid; i < 64 * 132; i += 256) { hsH[i] = 0u; hsL[i] = 0u; }
    __syncthreads();

    const int lane = tid & 31, wid = tid >> 5;
    const int mt = wid >> 1, nt = wid & 1;    // warp: m-tile (batch), n-tile (gatecols)
    const int grp = lane >> 2, tig = lane & 3;

    // preload B fragments (static for all steps): 16 k-steps x {bh0,bh1,bl0,bl1}
    unsigned bh0[16], bh1[16], bl0[16], bl1[16];
    {
        const int rb = (nt * 8 + grp) * 132 + tig;
#pragma unroll
        for (int ks = 0; ks < 16; ks++) {
            bh0[ks] = whH[rb + ks * 8];
            bh1[ks] = whH[rb + ks * 8 + 4];
            bl0[ks] = whL[rb + ks * 8];
            bl1[ks] = whL[rb + ks * 8 + 4];
        }
    }

    // ldmatrix source addresses for A (h) fragments
    const int arow = mt * 16 + (lane & 15);
    const int acol = ((lane >> 4) & 1) * 4;
    const unsigned aH_addr = smem_u32(hsH + arow * 132 + acol);
    const unsigned aL_addr = smem_u32(hsL + arow * 132 + acol);

    const int gb = tid >> 2, gj = tid & 3;    // gate-phase mapping

    for (int s = 0; s < NT; s++) {
        const int t = dir ? (NT - 1 - s) : s;
        float hprev = 0.f;
        if (s > 0) {
            const int tp = dir ? (t + 1) : (t - 1);
            const float4* hp = (const float4*)(out + (size_t)tp * NB * NH);
#pragma unroll 4
            for (int i = tid; i < NB * NH / 4; i += 256) {
                float4 v = __ldcg(hp + i);
                const int b = i >> 6, kp = (i & 63) * 2;
                unsigned h0, h1, l0, l1;
                bfsplit(v.x, v.y, h0, l0);
                bfsplit(v.z, v.w, h1, l1);
                *(uint2*)(hsH + b * 132 + kp) = make_uint2(h0, h1);
                *(uint2*)(hsL + b * 132 + kp) = make_uint2(l0, l1);
            }
            hprev = __ldcg(out + ((size_t)tp * NB + gb) * NH + j0 + gj);
        }
        __syncthreads();

        float acc[4] = {0.f, 0.f, 0.f, 0.f};
#pragma unroll
        for (int ks = 0; ks < 16; ks++) {
            unsigned aH[4], aL[4];
            LDSM_X4(aH, aH_addr + ks * 32);
            LDSM_X4(aL, aL_addr + ks * 32);
            MMA_BF16(acc, aH, bh0[ks], bh1[ks]);
            MMA_BF16(acc, aL, bh0[ks], bh1[ks]);
            MMA_BF16(acc, aH, bl0[ks], bl1[ks]);
        }
        // scatter accum: rows = batch, cols = gate col (nt*8 + tig*2 [+1])
        red[(nt * 8 + tig * 2    ) * 68 + mt * 16 + grp    ] = acc[0];
        red[(nt * 8 + tig * 2 + 1) * 68 + mt * 16 + grp    ] = acc[1];
        red[(nt * 8 + tig * 2    ) * 68 + mt * 16 + grp + 8] = acc[2];
        red[(nt * 8 + tig * 2 + 1) * 68 + mt * 16 + grp + 8] = acc[3];
        __syncthreads();

        const float gh0 = red[(0 + gj) * 68 + gb] + bsm[0 + gj];
        const float gh1 = red[(4 + gj) * 68 + gb] + bsm[4 + gj];
        const float gh2 = red[(8 + gj) * 68 + gb] + bsm[8 + gj];
        const float* gp = gx + ((size_t)t * NB + gb) * NG + j0 + gj;
        const float xr = gp[0], xz = gp[NH], xn = gp[2 * NH];
        const float r = 1.f / (1.f + expf(-(xr + gh0)));
        const float z = 1.f / (1.f + expf(-(xz + gh1)));
        const float n = tanhf(xn + r * gh2);
        const float hnew = (1.f - z) * n + z * hprev;
        out[((size_t)t * NB + gb) * NH + j0 + gj] = hnew;

        __threadfence();
        __syncthreads();
        if (tid == 0) ((volatile unsigned*)g_flags)[cta * 32] = (unsigned)(s + 1);
        if (tid < 128) {
            const unsigned tgt = (unsigned)(s + 1);
            while (((volatile unsigned*)g_flags)[tid * 32] < tgt) __nanosleep(32);
        }
        __syncthreads();
    }
}

// ---------------- Kernel 3: outputs = [out_f|out_b] @ Wout^T + bout (bf16x3) -
__global__ __launch_bounds__(256, 2) void gemm_proj_tc(
    const float* __restrict__ Wout, const float* __restrict__ bout,
    float* __restrict__ dst)
{
    extern __shared__ unsigned sm_u[];
    unsigned* Ah = sm_u;
    unsigned* Al = Ah + 128 * SST2;
    unsigned* Bh = Al + 128 * SST2;
    unsigned* Bl = Bh + 128 * SST2;

    const int m0 = blockIdx.x * 128;
    const int n0 = blockIdx.y * 128;
    const int tid = threadIdx.x;
    const int lane = tid & 31, warp = tid >> 5;
    const int wm = warp >> 1, wn = warp & 1;
    const int grp = lane >> 2, tig = lane & 3;

    float acc[2][8][4];
#pragma unroll
    for (int s = 0; s < 2; s++)
#pragma unroll
        for (int ns = 0; ns < 8; ns++)
#pragma unroll
            for (int q = 0; q < 4; q++) acc[s][ns][q] = 0.f;

    int srow[4], skc[4];
#pragma unroll
    for (int l = 0; l < 4; l++) { int idx = tid + l * 256; srow[l] = idx >> 3; skc[l] = (idx & 7) * 4; }

    float4 ra[4], rb[4];
#pragma unroll
    for (int l = 0; l < 4; l++) {
        ra[l] = *(const float4*)(g_out_f + (size_t)(m0 + srow[l]) * NH + skc[l]);
        rb[l] = *(const float4*)(Wout + (size_t)(n0 + srow[l]) * 512 + skc[l]);
    }

    for (int kt = 0; kt < 16; kt++) {
        __syncthreads();
#pragma unroll
        for (int l = 0; l < 4; l++) {
            const int off = srow[l] * SST2 + (skc[l] >> 1);
            unsigned h0, h1, l0, l1;
            bfsplit(ra[l].x, ra[l].y, h0, l0);
            bfsplit(ra[l].z, ra[l].w, h1, l1);
            *(uint2*)(Ah + off) = make_uint2(h0, h1);
            *(uint2*)(Al + off) = make_uint2(l0, l1);
            bfsplit(rb[l].x, rb[l].y, h0, l0);
            bfsplit(rb[l].z, rb[l].w, h1, l1);
            *(uint2*)(Bh + off) = make_uint2(h0, h1);
            *(uint2*)(Bl + off) = make_uint2(l0, l1);
        }
        __syncthreads();
        if (kt + 1 < 16) {
            const int k0 = (kt + 1) * 32;
            const float* Asrc = (k0 < 256) ? g_out_f : g_out_b;
            const int kk0 = k0 & 255;
#pragma unroll
            for (int l = 0; l < 4; l++) {
                ra[l] = *(const float4*)(Asrc + (size_t)(m0 + srow[l]) * NH + kk0 + skc[l]);
                rb[l] = *(const float4*)(Wout + (size_t)(n0 + srow[l]) * 512 + k0 + skc[l]);
            }
        }
#pragma unroll
        for (int kk = 0; kk < 2; kk++) {
            unsigned ah[2][4], al[2][4];
#pragma unroll
            for (int s = 0; s < 2; s++) {
                const int r = wm * 32 + s * 16 + grp;
                const int base = r * SST2 + kk * 8 + tig;
                ah[s][0] = Ah[base];            ah[s][1] = Ah[base + 8 * SST2];
                ah[s][2] = Ah[base + 4];        ah[s][3] = Ah[base + 8 * SST2 + 4];
                al[s][0] = Al[base];            al[s][1] = Al[base + 8 * SST2];
                al[s][2] = Al[base + 4];        al[s][3] = Al[base + 8 * SST2 + 4];
            }
#pragma unroll
            for (int ns = 0; ns < 8; ns++) {
                const int n = wn * 64 + ns * 8 + grp;
                const int nb = n * SST2 + kk * 8 + tig;
                const unsigned bh0 = Bh[nb], bh1 = Bh[nb + 4];
                const unsigned bl0 = Bl[nb], bl1 = Bl[nb + 4];
#pragma unroll
                for (int s = 0; s < 2; s++) {
                    MMA_BF16(acc[s][ns], ah[s], bh0, bh1);
                    MMA_BF16(acc[s][ns], al[s], bh0, bh1);
                    MMA_BF16(acc[s][ns], ah[s], bl0, bl1);
                }
            }
        }
    }

#pragma unroll
    for (int ns = 0; ns < 8; ns++) {
        const int cl = wn * 64 + ns * 8 + tig * 2;
        const float b0 = bout[n0 + cl], b1 = bout[n0 + cl + 1];
#pragma unroll
        for (int s = 0; s < 2; s++) {
            const int r = m0 + wm * 32 + s * 16 + grp;
            float* p0 = dst + (size_t)r * NH + n0 + cl;
            float* p1 = dst + (size_t)(r + 8) * NH + n0 + cl;
            *(float2*)p0 = make_float2(acc[s][ns][0] + b0, acc[s][ns][1] + b1);
            *(float2*)p1 = make_float2(acc[s][ns][2] + b0, acc[s][ns][3] + b1);
        }
    }
}

// ---------------- Kernel 4: hidden = tanh([h_f|h_b] @ Whid^T + bhid) --------
__global__ __launch_bounds__(256) void hidden_kernel(
    const float* __restrict__ Whid, const float* __restrict__ bhid,
    float* __restrict__ outh)
{
    __shared__ float hc[512];
    const int b = blockIdx.x, tid = threadIdx.x;
    hc[tid]       = g_out_f[((size_t)(NT - 1) * NB + b) * NH + tid];
    hc[256 + tid] = g_out_b[((size_t)b) * NH + tid];
    __syncthreads();
    const float* w = Whid + (size_t)tid * 512;
    float ssum = bhid[tid];
#pragma unroll 8
    for (int k = 0; k < 512; k++) ssum += hc[k] * w[k];
    outh[(size_t)b * NH + tid] = tanhf(ssum);
}

// ---------------- launcher ---------------------------------------------------
extern "C" void kernel_launch(void* const* d_in, const int* in_sizes, int n_in,
                              void* d_out, int out_size)
{
    const float* src   = (const float*)d_in[0];
    const float* Wih_f = (const float*)d_in[1];
    const float* Whh_f = (const float*)d_in[2];
    const float* bih_f = (const float*)d_in[3];
    const float* bhh_f = (const float*)d_in[4];
    const float* Wih_b = (const float*)d_in[5];
    const float* Whh_b = (const float*)d_in[6];
    const float* bih_b = (const float*)d_in[7];
    const float* bhh_b = (const float*)d_in[8];
    const float* Wout  = (const float*)d_in[9];
    const float* bout  = (const float*)d_in[10];
    const float* Whid  = (const float*)d_in[11];
    const float* bhid  = (const float*)d_in[12];
    float* out = (float*)d_out;

    const int gx_smem = 4 * 128 * SST2 * (int)sizeof(unsigned);  // 40960
    cudaFuncSetAttribute(gemm_gx_tc,
                         cudaFuncAttributeMaxDynamicSharedMemorySize, gx_smem);
    cudaFuncSetAttribute(gemm_proj_tc,
                         cudaFuncAttributeMaxDynamicSharedMemorySize, gx_smem);
    const int rec_smem = (64 * 132 * 2 + 16 * 132 * 2 + 16 * 68 + 16) * (int)sizeof(unsigned);
    cudaFuncSetAttribute(gru_rec_tc,
                         cudaFuncAttributeMaxDynamicSharedMemorySize, rec_smem);

    init_flags_kernel<<<1, 128>>>();
    gemm_gx_tc<<<dim3(256, 12), 256, gx_smem>>>(src, Wih_f, Wih_b, bih_f, bih_b);
    gru_rec_tc<<<128, 256, rec_smem>>>(Whh_f, bhh_f, Whh_b, bhh_b);
    gemm_proj_tc<<<dim3(256, 2), 256, gx_smem>>>(Wout, bout, out);
    hidden_kernel<<<64, 256>>>(Whid, bhid, out + (size_t)NT * NB * NH);
}

// round 5
// speedup vs baseline: 1.7173x; 1.1123x over previous
#include <cuda_runtime.h>
#include <cuda_bf16.h>
#include <math.h>

#define NT 512
#define NB 64
#define NI 1024
#define NH 256
#define NG 768   // 3*NH

// ---------------- scratch (device globals: no allocations allowed) ----------
__device__ float    g_gx_f[NT * NB * NG];     // 100.7 MB
__device__ float    g_gx_b[NT * NB * NG];     // 100.7 MB
__device__ unsigned g_srcH[32768 * 512];      // src bf16-hi k-pairs
__device__ unsigned g_srcL[32768 * 512];      // src bf16-lo k-pairs
__device__ unsigned g_wH[1536 * 512];         // Wih_f|Wih_b hi
__device__ unsigned g_wL[1536 * 512];         // Wih_f|Wih_b lo
__device__ unsigned g_woH[256 * 256];         // Wout hi
__device__ unsigned g_woL[256 * 256];         // Wout lo
__device__ unsigned g_poutH[32768 * 256];     // h history hi: [t*64+b][fwd 0..127 | bwd 128..255]
__device__ unsigned g_poutL[32768 * 256];     // h history lo
__device__ unsigned g_flags[128 * 32];        // barrier flags, 128B apart

__global__ void init_flags_kernel() {
    if (threadIdx.x < 128)
        ((volatile unsigned*)g_flags)[threadIdx.x * 32] = 0u;
}

// ---------------- helpers ----------------------------------------------------
__device__ __forceinline__ void bfsplit(float x, float y, unsigned& hi, unsigned& lo) {
    unsigned short bx = __bfloat16_as_ushort(__float2bfloat16_rn(x));
    unsigned short by = __bfloat16_as_ushort(__float2bfloat16_rn(y));
    hi = (unsigned)bx | ((unsigned)by << 16);
    float fx = __uint_as_float((unsigned)bx << 16);
    float fy = __uint_as_float((unsigned)by << 16);
    __nv_bfloat162 t = __floats2bfloat162_rn(x - fx, y - fy);
    lo = reinterpret_cast<unsigned&>(t);
}

#define MMA_BF16(d, a, b0, b1)                                                  \
    asm volatile("mma.sync.aligned.m16n8k16.row.col.f32.bf16.bf16.f32 "         \
        "{%0,%1,%2,%3}, {%4,%5,%6,%7}, {%8,%9}, {%0,%1,%2,%3};"                 \
        : "+f"(d[0]), "+f"(d[1]), "+f"(d[2]), "+f"(d[3])                        \
        : "r"(a[0]), "r"(a[1]), "r"(a[2]), "r"(a[3]), "r"(b0), "r"(b1))

#define LDSM_X4(r, addr)                                                        \
    asm volatile("ldmatrix.sync.aligned.m8n8.x4.shared.b16 {%0,%1,%2,%3}, [%4];"\
        : "=r"((r)[0]), "=r"((r)[1]), "=r"((r)[2]), "=r"((r)[3]) : "r"(addr))

__device__ __forceinline__ void cp16(unsigned smem_dst, const void* gsrc) {
    asm volatile("cp.async.cg.shared.global [%0], [%1], 16;"
                 :: "r"(smem_dst), "l"(gsrc));
}
#define CP_COMMIT() asm volatile("cp.async.commit_group;")
#define CP_WAIT(n)  asm volatile("cp.async.wait_group %0;" :: "n"(n))

__device__ __forceinline__ unsigned smem_u32(const void* p) {
    return (unsigned)__cvta_generic_to_shared(p);
}
__device__ __forceinline__ unsigned ld_acq(const unsigned* p) {
    unsigned v; asm volatile("ld.acquire.gpu.global.u32 %0, [%1];" : "=r"(v) : "l"(p));
    return v;
}

// ---------------- conversion kernels (run once per launch) ------------------
__global__ __launch_bounds__(256) void conv_src_kernel(const float* __restrict__ a) {
    const int i = blockIdx.x * 256 + threadIdx.x;        // 65536 blocks -> 16.7M
    float2 v = ((const float2*)a)[i];
    unsigned h, l; bfsplit(v.x, v.y, h, l);
    g_srcH[i] = h; g_srcL[i] = l;
}
__global__ __launch_bounds__(256) void conv_wih_kernel(
    const float* __restrict__ f, const float* __restrict__ b) {
    const int i = blockIdx.x * 256 + threadIdx.x;        // 1536 blocks -> 393216
    float2 v = ((const float2*)f)[i];
    unsigned h, l; bfsplit(v.x, v.y, h, l);
    g_wH[i] = h; g_wL[i] = l;
    float2 w = ((const float2*)b)[i];
    bfsplit(w.x, w.y, h, l);
    g_wH[768 * 512 + i] = h; g_wL[768 * 512 + i] = l;
}
__global__ __launch_bounds__(256) void conv_wout_kernel(const float* __restrict__ a) {
    const int i = blockIdx.x * 256 + threadIdx.x;        // 256 blocks -> 65536
    float2 v = ((const float2*)a)[i];
    unsigned h, l; bfsplit(v.x, v.y, h, l);
    g_woH[i] = h; g_woL[i] = l;
}

// ---------------- shared mma tile compute (128x128 tile, 8 warps) -----------
#define SST2 20
#define PB (128 * SST2)     // u32 per plane

__device__ __forceinline__ void mma_tile_compute(
    const unsigned* Ah, const unsigned* Al, const unsigned* Bh, const unsigned* Bl,
    float acc[2][8][4], int wm, int wn, int grp, int tig)
{
#pragma unroll
    for (int kk = 0; kk < 2; kk++) {
        unsigned ah[2][4], al[2][4];
#pragma unroll
        for (int s = 0; s < 2; s++) {
            const int r = wm * 32 + s * 16 + grp;
            const int base = r * SST2 + kk * 8 + tig;
            ah[s][0] = Ah[base];            ah[s][1] = Ah[base + 8 * SST2];
            ah[s][2] = Ah[base + 4];        ah[s][3] = Ah[base + 8 * SST2 + 4];
            al[s][0] = Al[base];            al[s][1] = Al[base + 8 * SST2];
            al[s][2] = Al[base + 4];        al[s][3] = Al[base + 8 * SST2 + 4];
        }
#pragma unroll
        for (int ns = 0; ns < 8; ns++) {
            const int n = wn * 64 + ns * 8 + grp;
            const int nb = n * SST2 + kk * 8 + tig;
            const unsigned bh0 = Bh[nb], bh1 = Bh[nb + 4];
            const unsigned bl0 = Bl[nb], bl1 = Bl[nb + 4];
#pragma unroll
            for (int s = 0; s < 2; s++) {
                MMA_BF16(acc[s][ns], ah[s], bh0, bh1);
                MMA_BF16(acc[s][ns], al[s], bh0, bh1);
                MMA_BF16(acc[s][ns], ah[s], bl0, bl1);
            }
        }
    }
}

// ---------------- Kernel 1: gx = src @ Wih^T + bih --------------------------
// A/B staged from pre-split planes via double-buffered cp.async.
__global__ __launch_bounds__(256, 2) void gemm_gx_tc(
    const float* __restrict__ bih_f, const float* __restrict__ bih_b)
{
    extern __shared__ unsigned sm[];
    const unsigned sbase = smem_u32(sm);

    const int m0 = blockIdx.x * 128;
    const int n0 = blockIdx.y * 128;
    const bool fwd = (n0 < NG);
    const float* bias = fwd ? (bih_f + n0) : (bih_b + (n0 - NG));
    float* outp = fwd ? g_gx_f : g_gx_b;
    const int nc0 = fwd ? n0 : (n0 - NG);

    const int tid = threadIdx.x;
    const int lane = tid & 31, warp = tid >> 5;
    const int wm = warp >> 1, wn = warp & 1;
    const int grp = lane >> 2, tig = lane & 3;
    const int r0 = tid >> 2, c0 = (tid & 3) * 4;

    float acc[2][8][4];
#pragma unroll
    for (int s = 0; s < 2; s++)
#pragma unroll
        for (int ns = 0; ns < 8; ns++)
#pragma unroll
            for (int q = 0; q < 4; q++) acc[s][ns][q] = 0.f;

    auto issue = [&](int kt, int buf) {
        const unsigned b = sbase + (unsigned)buf * 4u * PB * 4u;
#pragma unroll
        for (int l = 0; l < 2; l++) {
            const int row = r0 + l * 64;
            const unsigned d = b + (unsigned)(row * SST2 + c0) * 4u;
            const size_t ga = (size_t)(m0 + row) * 512 + kt * 16 + c0;
            const size_t gb = (size_t)(n0 + row) * 512 + kt * 16 + c0;
            cp16(d,              g_srcH + ga);
            cp16(d + PB * 4,     g_srcL + ga);
            cp16(d + 2 * PB * 4, g_wH + gb);
            cp16(d + 3 * PB * 4, g_wL + gb);
        }
        CP_COMMIT();
    };

    issue(0, 0);
    issue(1, 1);
    for (int kt = 0; kt < 32; kt++) {
        if (kt == 31) { CP_WAIT(0); } else { CP_WAIT(1); }
        __syncthreads();
        const unsigned* bp = sm + (kt & 1) * 4 * PB;
        mma_tile_compute(bp, bp + PB, bp + 2 * PB, bp + 3 * PB, acc, wm, wn, grp, tig);
        __syncthreads();
        if (kt + 2 < 32) issue(kt + 2, kt & 1);
    }

#pragma unroll
    for (int ns = 0; ns < 8; ns++) {
        const int cl = wn * 64 + ns * 8 + tig * 2;
        const float b0 = bias[cl], b1 = bias[cl + 1];
#pragma unroll
        for (int s = 0; s < 2; s++) {
            const int r = m0 + wm * 32 + s * 16 + grp;
            float* p0 = outp + (size_t)r * NG + nc0 + cl;
            float* p1 = outp + (size_t)(r + 8) * NG + nc0 + cl;
            *(float2*)p0 = make_float2(acc[s][ns][0] + b0, acc[s][ns][1] + b1);
            *(float2*)p1 = make_float2(acc[s][ns][2] + b0, acc[s][ns][3] + b1);
        }
    }
}

// ---------------- Kernel 2: persistent GRU recurrence (tensor cores) --------
// h exchanged as pre-split bf16 planes (written by producer quads), staged by
// cp.async; hprev carried in register; per-direction flag barrier.
__global__ __launch_bounds__(256) void gru_rec_tc(
    const float* __restrict__ Whh_f, const float* __restrict__ bhh_f,
    const float* __restrict__ Whh_b, const float* __restrict__ bhh_b)
{
    extern __shared__ unsigned smu[];
    unsigned* hsH = smu;                      // [64][132]
    unsigned* hsL = hsH + 64 * 132;
    unsigned* whH = hsL + 64 * 132;           // [16][132]
    unsigned* whL = whH + 16 * 132;
    float*    red = (float*)(whL + 16 * 132); // [16][68]
    float*    bsm = red + 16 * 68;            // [12]

    const int cta = blockIdx.x;
    const int tid = threadIdx.x;
    const int dir = cta >> 6;
    const int j0  = (cta & 63) * 4;
    const float* Whh = dir ? Whh_b : Whh_f;
    const float* bhh = dir ? bhh_b : bhh_f;
    const float* gx  = dir ? g_gx_b : g_gx_f;

    // Whh slice -> bf16 hi/lo smem planes (rows 12..15 zero padding)
    for (int idx = tid; idx < 16 * 128; idx += 256) {
        const int row = idx >> 7, col = idx & 127;
        unsigned hi = 0u, lo = 0u;
        if (row < 12) {
            const float* wr = Whh + (size_t)((row >> 2) * NH + j0 + (row & 3)) * NH + col * 2;
            bfsplit(wr[0], wr[1], hi, lo);
        }
        whH[row * 132 + col] = hi;
        whL[row * 132 + col] = lo;
    }
    if (tid < 12) bsm[tid] = bhh[(tid >> 2) * NH + j0 + (tid & 3)];
    for (int i = tid; i < 64 * 132; i += 256) { hsH[i] = 0u; hsL[i] = 0u; }
    __syncthreads();

    const int lane = tid & 31, wid = tid >> 5;
    const int mt = wid >> 1, nt = wid & 1;
    const int grp = lane >> 2, tig = lane & 3;

    unsigned bh0[16], bh1[16], bl0[16], bl1[16];
    {
        const int rb = (nt * 8 + grp) * 132 + tig;
#pragma unroll
        for (int ks = 0; ks < 16; ks++) {
            bh0[ks] = whH[rb + ks * 8];
            bh1[ks] = whH[rb + ks * 8 + 4];
            bl0[ks] = whL[rb + ks * 8];
            bl1[ks] = whL[rb + ks * 8 + 4];
        }
    }

    const int arow = mt * 16 + (lane & 15);
    const int acol = ((lane >> 4) & 1) * 4;
    const unsigned aH_addr = smem_u32(hsH + arow * 132 + acol);
    const unsigned aL_addr = smem_u32(hsL + arow * 132 + acol);
    const unsigned hsH_b = smem_u32(hsH);
    const unsigned hsL_b = smem_u32(hsL);

    const int gb = tid >> 2, gj = tid & 3;
    float hprev = 0.f;

    for (int s = 0; s < NT; s++) {
        const int t = dir ? (NT - 1 - s) : s;
        // prefetch gate inputs (independent of h staging)
        const float* gp = gx + ((size_t)t * NB + gb) * NG + j0 + gj;
        const float xr = __ldg(gp), xz = __ldg(gp + NH), xn = __ldg(gp + 2 * NH);

        if (s > 0) {
            const int tp = dir ? (t + 1) : (t - 1);
            const unsigned* srcH = g_poutH + ((size_t)tp * NB) * 256 + dir * 128;
            const unsigned* srcL = g_poutL + ((size_t)tp * NB) * 256 + dir * 128;
#pragma unroll
            for (int l = 0; l < 8; l++) {
                const int u = tid + l * 256;
                const int row = u >> 5, c4 = (u & 31) * 4;
                cp16(hsH_b + (unsigned)(row * 132 + c4) * 4u, srcH + row * 256 + c4);
                cp16(hsL_b + (unsigned)(row * 132 + c4) * 4u, srcL + row * 256 + c4);
            }
            CP_COMMIT();
            CP_WAIT(0);
        }
        __syncthreads();

        float acc[4] = {0.f, 0.f, 0.f, 0.f};
#pragma unroll
        for (int ks = 0; ks < 16; ks++) {
            unsigned aH[4], aL[4];
            LDSM_X4(aH, aH_addr + ks * 32);
            LDSM_X4(aL, aL_addr + ks * 32);
            MMA_BF16(acc, aH, bh0[ks], bh1[ks]);
            MMA_BF16(acc, aL, bh0[ks], bh1[ks]);
            MMA_BF16(acc, aH, bl0[ks], bl1[ks]);
        }
        red[(nt * 8 + tig * 2    ) * 68 + mt * 16 + grp    ] = acc[0];
        red[(nt * 8 + tig * 2 + 1) * 68 + mt * 16 + grp    ] = acc[1];
        red[(nt * 8 + tig * 2    ) * 68 + mt * 16 + grp + 8] = acc[2];
        red[(nt * 8 + tig * 2 + 1) * 68 + mt * 16 + grp + 8] = acc[3];
        __syncthreads();

        const float gh0 = red[(0 + gj) * 68 + gb] + bsm[0 + gj];
        const float gh1 = red[(4 + gj) * 68 + gb] + bsm[4 + gj];
        const float gh2 = red[(8 + gj) * 68 + gb] + bsm[8 + gj];
        const float r = 1.f / (1.f + expf(-(xr + gh0)));
        const float z = 1.f / (1.f + expf(-(xz + gh1)));
        const float n = tanhf(xn + r * gh2);
        const float hnew = (1.f - z) * n + z * hprev;
        hprev = hnew;

        // quad leader packs 4 cols -> bf16 hi/lo plane words
        const float v0 = __shfl_sync(0xffffffffu, hnew, (lane & ~3) | 0);
        const float v1 = __shfl_sync(0xffffffffu, hnew, (lane & ~3) | 1);
        const float v2 = __shfl_sync(0xffffffffu, hnew, (lane & ~3) | 2);
        const float v3 = __shfl_sync(0xffffffffu, hnew, (lane & ~3) | 3);
        if (gj == 0) {
            unsigned hA, lA, hB, lB;
            bfsplit(v0, v1, hA, lA);
            bfsplit(v2, v3, hB, lB);
            const size_t rowm = (size_t)t * NB + gb;
            *(uint2*)(g_poutH + rowm * 256 + dir * 128 + (j0 >> 1)) = make_uint2(hA, hB);
            *(uint2*)(g_poutL + rowm * 256 + dir * 128 + (j0 >> 1)) = make_uint2(lA, lB);
        }

        if (s + 1 < NT) {
            __threadfence();
            __syncthreads();
            if (tid == 0) ((volatile unsigned*)g_flags)[cta * 32] = (unsigned)(s + 1);
            if (tid < 64) {
                const unsigned* fp = g_flags + (dir * 64 + tid) * 32;
                const unsigned tgt = (unsigned)(s + 1);
                while (ld_acq(fp) < tgt) {}
            }
            __syncthreads();
        }
    }
}

// ---------------- Kernel 3: outputs = h_hist @ Wout^T + bout ----------------
// A = pre-split h planes written by the recurrence; B = pre-split Wout.
__global__ __launch_bounds__(256, 2) void gemm_proj_tc(
    const float* __restrict__ bout, float* __restrict__ dst)
{
    extern __shared__ unsigned sm[];
    const unsigned sbase = smem_u32(sm);

    const int m0 = blockIdx.x * 128;
    const int n0 = blockIdx.y * 128;
    const int tid = threadIdx.x;
    const int lane = tid & 31, warp = tid >> 5;
    const int wm = warp >> 1, wn = warp & 1;
    const int grp = lane >> 2, tig = lane & 3;
    const int r0 = tid >> 2, c0 = (tid & 3) * 4;

    float acc[2][8][4];
#pragma unroll
    for (int s = 0; s < 2; s++)
#pragma unroll
        for (int ns = 0; ns < 8; ns++)
#pragma unroll
            for (int q = 0; q < 4; q++) acc[s][ns][q] = 0.f;

    auto issue = [&](int kt, int buf) {
        const unsigned b = sbase + (unsigned)buf * 4u * PB * 4u;
#pragma unroll
        for (int l = 0; l < 2; l++) {
            const int row = r0 + l * 64;
            const unsigned d = b + (unsigned)(row * SST2 + c0) * 4u;
            const size_t ga = (size_t)(m0 + row) * 256 + kt * 16 + c0;
            const size_t gb = (size_t)(n0 + row) * 256 + kt * 16 + c0;
            cp16(d,              g_poutH + ga);
            cp16(d + PB * 4,     g_poutL + ga);
            cp16(d + 2 * PB * 4, g_woH + gb);
            cp16(d + 3 * PB * 4, g_woL + gb);
        }
        CP_COMMIT();
    };

    issue(0, 0);
    issue(1, 1);
    for (int kt = 0; kt < 16; kt++) {
        if (kt == 15) { CP_WAIT(0); } else { CP_WAIT(1); }
        __syncthreads();
        const unsigned* bp = sm + (kt & 1) * 4 * PB;
        mma_tile_compute(bp, bp + PB, bp + 2 * PB, bp + 3 * PB, acc, wm, wn, grp, tig);
        __syncthreads();
        if (kt + 2 < 16) issue(kt + 2, kt & 1);
    }

#pragma unroll
    for (int ns = 0; ns < 8; ns++) {
        const int cl = wn * 64 + ns * 8 + tig * 2;
        const float b0 = bout[n0 + cl], b1 = bout[n0 + cl + 1];
#pragma unroll
        for (int s = 0; s < 2; s++) {
            const int r = m0 + wm * 32 + s * 16 + grp;
            float* p0 = dst + (size_t)r * NH + n0 + cl;
            float* p1 = dst + (size_t)(r + 8) * NH + n0 + cl;
            *(float2*)p0 = make_float2(acc[s][ns][0] + b0, acc[s][ns][1] + b1);
            *(float2*)p1 = make_float2(acc[s][ns][2] + b0, acc[s][ns][3] + b1);
        }
    }
}

// ---------------- Kernel 4: hidden = tanh([h_f|h_b] @ Whid^T + bhid) --------
__global__ __launch_bounds__(256) void hidden_kernel(
    const float* __restrict__ Whid, const float* __restrict__ bhid,
    float* __restrict__ outh)
{
    __shared__ float hc[512];
    const int b = blockIdx.x, tid = threadIdx.x;
    // tid<128: fwd final h (t=511) kp 0..127; tid>=128: bwd final h (t=0) kp 128..255
    const size_t row = (tid < 128) ? ((size_t)(NT - 1) * NB + b) : (size_t)b;
    const unsigned hH = g_poutH[row * 256 + tid];
    const unsigned hL = g_poutL[row * 256 + tid];
    hc[2 * tid]     = __uint_as_float((hH & 0xffffu) << 16) +
                      __uint_as_float((hL & 0xffffu) << 16);
    hc[2 * tid + 1] = __uint_as_float(hH & 0xffff0000u) +
                      __uint_as_float(hL & 0xffff0000u);
    __syncthreads();
    const float* w = Whid + (size_t)tid * 512;
    float ssum = bhid[tid];
#pragma unroll 8
    for (int k = 0; k < 512; k++) ssum += hc[k] * w[k];
    outh[(size_t)b * NH + tid] = tanhf(ssum);
}

// ---------------- launcher ---------------------------------------------------
extern "C" void kernel_launch(void* const* d_in, const int* in_sizes, int n_in,
                              void* d_out, int out_size)
{
    const float* src   = (const float*)d_in[0];
    const float* Wih_f = (const float*)d_in[1];
    const float* Whh_f = (const float*)d_in[2];
    const float* bih_f = (const float*)d_in[3];
    const float* bhh_f = (const float*)d_in[4];
    const float* Wih_b = (const float*)d_in[5];
    const float* Whh_b = (const float*)d_in[6];
    const float* bih_b = (const float*)d_in[7];
    const float* bhh_b = (const float*)d_in[8];
    const float* Wout  = (const float*)d_in[9];
    const float* bout  = (const float*)d_in[10];
    const float* Whid  = (const float*)d_in[11];
    const float* bhid  = (const float*)d_in[12];
    float* out = (float*)d_out;

    const int gemm_smem = 2 * 4 * PB * (int)sizeof(unsigned);   // 81920
    cudaFuncSetAttribute(gemm_gx_tc,
                         cudaFuncAttributeMaxDynamicSharedMemorySize, gemm_smem);
    cudaFuncSetAttribute(gemm_proj_tc,
                         cudaFuncAttributeMaxDynamicSharedMemorySize, gemm_smem);
    const int rec_smem = (64 * 132 * 2 + 16 * 132 * 2 + 16 * 68 + 16) * (int)sizeof(unsigned);
    cudaFuncSetAttribute(gru_rec_tc,
                         cudaFuncAttributeMaxDynamicSharedMemorySize, rec_smem);

    init_flags_kernel<<<1, 128>>>();
    conv_src_kernel<<<65536, 256>>>(src);
    conv_wih_kernel<<<1536, 256>>>(Wih_f, Wih_b);
    conv_wout_kernel<<<256, 256>>>(Wout);
    gemm_gx_tc<<<dim3(256, 12), 256, gemm_smem>>>(bih_f, bih_b);
    gru_rec_tc<<<128, 256, rec_smem>>>(Whh_f, bhh_f, Whh_b, bhh_b);
    gemm_proj_tc<<<dim3(256, 2), 256, gemm_smem>>>(bout, out);
    hidden_kernel<<<64, 256>>>(Whid, bhid, out + (size_t)NT * NB * NH);
}